// round 12
// baseline (speedup 1.0000x reference)
#include <cuda_runtime.h>
#include <math.h>
#include <stdint.h>

#define NPIX 4096
#define PADW 66
#define PADN 4356
#define BATCH 2
#define CVCH 256
#define CQKCH 320
#define DPCH 64
#define NHID 128

// ---------------- scratch arena ----------------
constexpr size_t SZ_QK = (size_t)BATCH * CQKCH * NPIX;
constexpr size_t SZ_CV = (size_t)BATCH * CVCH * NPIX;
constexpr size_t SZ_DP = (size_t)BATCH * DPCH * NPIX;

constexpr size_t OFF_QUERY = 0;
constexpr size_t OFF_KEYT  = OFF_QUERY + SZ_QK;
constexpr size_t OFF_QF    = OFF_KEYT + SZ_QK;
constexpr size_t OFF_KF    = OFF_QF + SZ_QK;
constexpr size_t OFF_QP    = OFF_KF + SZ_QK;
constexpr size_t OFF_KP    = OFF_QP + SZ_DP;
constexpr size_t OFF_VH    = OFF_KP + SZ_DP;
constexpr size_t OFF_OUT   = OFF_VH + SZ_CV;
constexpr size_t OFF_STATS = OFF_OUT + SZ_CV;
constexpr size_t OFF_CONF  = OFF_STATS + (size_t)BATCH*NPIX*4;
constexpr size_t OFF_ACTV  = OFF_CONF + (size_t)BATCH*NPIX;
constexpr size_t OFF_GAMMA = OFF_ACTV + (size_t)BATCH*NHID*PADN;
constexpr size_t OFF_BETA  = OFF_GAMMA + SZ_CV;
constexpr size_t OFF_INST  = OFF_BETA + SZ_CV;
constexpr size_t OFF_YPRE  = OFF_INST + (size_t)BATCH*CVCH*2;
constexpr size_t OFF_PST   = OFF_YPRE + SZ_CV;
constexpr size_t OFF_YPAD  = OFF_PST + (size_t)BATCH*NPIX*2;
constexpr size_t OFF_T1PAD = OFF_YPAD + (size_t)BATCH*CVCH*PADN;
constexpr size_t OFF_SEGP  = OFF_T1PAD + (size_t)BATCH*CVCH*PADN;
constexpr size_t OFF_VHT   = OFF_SEGP + 26176;
constexpr size_t OFF_V2T   = OFF_VHT + SZ_CV;
constexpr size_t OFF_WT    = OFF_V2T + SZ_CV;
constexpr size_t WT_F   = 0;
constexpr size_t WT_G   = WT_F  + 320*320;
constexpr size_t WT_H   = WT_G  + 320*320;
constexpr size_t WT_FP  = WT_H  + 256*256;
constexpr size_t WT_GP  = WT_FP + 320*64;
constexpr size_t WT_SPS = WT_GP + 320*64;
constexpr size_t WT_SPG = WT_SPS + 9*3*128;
constexpr size_t WT_SPB = WT_SPG + 9*128*256;
constexpr size_t WT_R1  = WT_SPB + 9*128*256;
constexpr size_t WT_R2  = WT_R1  + 9*256*256;
constexpr size_t WT_END = WT_R2  + 9*256*256;
constexpr size_t OFF_MASK = OFF_WT + ((WT_END + 63) & ~(size_t)63);
constexpr size_t ARENA_FLOATS = OFF_MASK + ((size_t)BATCH*NPIX*NPIX)/4 + 64;

__device__ __align__(16) float g_arena[ARENA_FLOATS];

// ---------------- helpers ----------------
__device__ __forceinline__ uint32_t f2tf32(float v){
    uint32_t r;
    asm("cvt.rna.tf32.f32 %0, %1;" : "=r"(r) : "f"(v));
    return r;
}
__device__ __forceinline__ float tf(float v){ return __uint_as_float(f2tf32(v)); }

__device__ __forceinline__ void mma_tf32(float* d, const uint32_t* a, const uint32_t* b){
    asm volatile("mma.sync.aligned.m16n8k8.row.col.f32.tf32.tf32.f32 "
        "{%0,%1,%2,%3}, {%4,%5,%6,%7}, {%8,%9}, {%0,%1,%2,%3};"
        : "+f"(d[0]), "+f"(d[1]), "+f"(d[2]), "+f"(d[3])
        : "r"(a[0]), "r"(a[1]), "r"(a[2]), "r"(a[3]), "r"(b[0]), "r"(b[1]));
}

__device__ __forceinline__ float fast_exp(float x){
    float t = x * 1.4426950408889634f;
    t = fmaxf(t, -126.0f);
    float tr = t + 12582912.0f;
    int   k  = __float_as_int(tr) - 0x4B400000;
    float fi = tr - 12582912.0f;
    float f  = t - fi;
    float p = 1.0f + f*(0.6931471805599453f + f*(0.2402265069591007f
              + f*(0.0555041086648216f + f*0.0096181291076285f)));
    return p * __int_as_float((k + 127) << 23);
}

// ---------------- utility kernels ----------------
__global__ void zero_kernel(float* p, int n){
    int i = blockIdx.x * blockDim.x + threadIdx.x;
    if (i < n) p[i] = 0.f;
}

__global__ void transpose_w(const float* __restrict__ src, float* __restrict__ dst,
                            int M, int K, int taps){
    int idx = blockIdx.x * blockDim.x + threadIdx.x;
    if (idx >= M * K * taps) return;
    int t = idx / (K * M);
    int r = idx % (K * M);
    int k = r / M;
    int m = r % M;
    dst[idx] = src[((size_t)m * K + k) * taps + t];
}

// [b][c][m] -> [b][m][c]
__global__ __launch_bounds__(256) void transpose_cm(const float* __restrict__ src,
                                                    float* __restrict__ dst){
    __shared__ float s[32][33];
    int mBase = blockIdx.x * 32, cBase = blockIdx.y * 32, b = blockIdx.z;
    int tx = threadIdx.x & 31, ty = threadIdx.x >> 5;
    size_t base = (size_t)b * CVCH * NPIX;
#pragma unroll
    for (int i = 0; i < 4; ++i){
        int c = cBase + ty + i * 8;
        s[ty + i * 8][tx] = src[base + (size_t)c * NPIX + mBase + tx];
    }
    __syncthreads();
#pragma unroll
    for (int i = 0; i < 4; ++i){
        int m = mBase + ty + i * 8;
        dst[base + (size_t)m * CVCH + cBase + tx] = s[tx][ty + i * 8];
    }
}

__global__ void pad_seg(const float* __restrict__ seg, float* __restrict__ dst){
    int idx = blockIdx.x * blockDim.x + threadIdx.x;
    if (idx >= BATCH * 3 * PADN) return;
    int bc = idx / PADN;
    int r = idx % PADN;
    int yy = r / PADW, xx = r % PADW;
    float v = 0.f;
    if (yy >= 1 && yy <= 64 && xx >= 1 && xx <= 64)
        v = seg[(size_t)bc * NPIX + (yy - 1) * 64 + (xx - 1)];
    dst[idx] = v;
}

__global__ __launch_bounds__(256) void norm_concat(
    const float* __restrict__ q, const float* __restrict__ k,
    const float* __restrict__ pos, float* __restrict__ outq, float* __restrict__ outk){
    const float* src = blockIdx.y ? k : q;
    float* dst = blockIdx.y ? outk : outq;
    int b = blockIdx.x / 64, y = blockIdx.x % 64;
    int tid = threadIdx.x;
    int x = tid & 63, cl = tid >> 6;
    const float* sb = src + (size_t)b * CVCH * NPIX + y * 64;
    __shared__ float partial[4][64];
    __shared__ float inv[64];
    float ss = 0.f;
    for (int c = cl; c < CVCH; c += 4){ float v = sb[(size_t)c * NPIX + x]; ss += v * v; }
    partial[cl][x] = ss;
    __syncthreads();
    if (cl == 0){
        float s = partial[0][x] + partial[1][x] + partial[2][x] + partial[3][x];
        inv[x] = 1.f / (sqrtf(s) + 2.220446049250313e-16f);
    }
    __syncthreads();
    float* db = dst + (size_t)b * CQKCH * NPIX + y * 64;
    float iv = inv[x];
    for (int c = cl; c < CVCH; c += 4) db[(size_t)c * NPIX + x] = sb[(size_t)c * NPIX + x] * iv;
    const float* pb = pos + y * 64;
    for (int i = tid; i < 64 * 64; i += 256){
        int cp = i >> 6, xx = i & 63;
        db[(size_t)(CVCH + cp) * NPIX + xx] = pb[(size_t)cp * NPIX + xx];
    }
}

// ------------- exact-fp32 1x1 conv GEMM (QP/KP — mask sign sensitivity) -------------
__global__ __launch_bounds__(256) void gemm_wx_f32(
    const float* __restrict__ Wt, const float* __restrict__ X,
    const float* __restrict__ bias, float* __restrict__ Cout,
    int M, int K, long xBatchStride, int xChanStride, long cBatchStride)
{
    int b = blockIdx.z;
    int n0 = blockIdx.x * 64;
    int m0 = blockIdx.y * 64;
    const float* Xb = X + (size_t)b * xBatchStride;
    __shared__ __align__(16) float As[16][64];
    __shared__ __align__(16) float Bs[16][64];
    float acc[4][4] = {};
    int tid = threadIdx.x;
    int tx = tid & 15, ty = tid >> 4;
    for (int k0 = 0; k0 < K; k0 += 16){
#pragma unroll
        for (int i = 0; i < 4; ++i){
            int idx = tid + 256 * i;
            int kk = idx >> 6, col = idx & 63;
            int kg = k0 + kk;
            As[kk][col] = (kg < K) ? Wt[(size_t)kg * M + m0 + col] : 0.f;
            Bs[kk][col] = (kg < K) ? Xb[(size_t)kg * xChanStride + n0 + col] : 0.f;
        }
        __syncthreads();
#pragma unroll
        for (int kk = 0; kk < 16; ++kk){
            float4 a  = *(const float4*)&As[kk][ty * 4];
            float4 bb = *(const float4*)&Bs[kk][tx * 4];
            float av[4] = {a.x, a.y, a.z, a.w};
            float bv[4] = {bb.x, bb.y, bb.z, bb.w};
#pragma unroll
            for (int i = 0; i < 4; ++i)
#pragma unroll
                for (int j = 0; j < 4; ++j)
                    acc[i][j] += av[i] * bv[j];
        }
        __syncthreads();
    }
#pragma unroll
    for (int i = 0; i < 4; ++i){
        int m = m0 + ty * 4 + i;
        float bvv = bias ? bias[m] : 0.f;
#pragma unroll
        for (int j = 0; j < 4; ++j)
            Cout[(size_t)b * cBatchStride + (size_t)m * NPIX + n0 + tx * 4 + j] = acc[i][j] + bvv;
    }
}

// ------------- tf32 tensor GEMM: block 128Mx128N, warp 64x32 -------------
__global__ __launch_bounds__(256, 1) void gemm_tf32(
    const float* __restrict__ A, long aBatchStride, int aRowStride, int M,
    const float* __restrict__ X, long xBatchStride, int xChanStride,
    const float* __restrict__ bias, float* __restrict__ Cout, long cBatchStride,
    int K, int taps, int relu, int outPadded, float scale,
    const float* __restrict__ addsrc, long addBatchStride)
{
    int b = blockIdx.z;
    int n0 = blockIdx.x * 128;
    int m0 = blockIdx.y * 128;
    const float* A_ = A + (size_t)b * aBatchStride;
    const float* Xb = X + (size_t)b * xBatchStride;
    __shared__ float As[16][136];
    __shared__ float Bs[16][136];
    int tid = threadIdx.x;
    int wid = tid >> 5, lane = tid & 31;
    int gid = lane >> 2, tig = lane & 3;
    int warpM = wid & 1, warpN = wid >> 1;
    float acc[4][4][4];
#pragma unroll
    for (int mi = 0; mi < 4; ++mi)
#pragma unroll
        for (int ni = 0; ni < 4; ++ni)
#pragma unroll
            for (int p = 0; p < 4; ++p) acc[mi][ni][p] = 0.f;

    int Ktot = K * taps;
    for (int k0 = 0; k0 < Ktot; k0 += 16){
        // A: 128 wide, 2 float4 per thread
#pragma unroll
        for (int i = 0; i < 2; ++i){
            int qi = tid + i * 256;
            int kk = qi >> 5, m = (qi & 31) * 4;
            int kg = k0 + kk;
            float4 v = make_float4(0.f, 0.f, 0.f, 0.f);
            if (kg < Ktot && m0 + m < M)
                v = *(const float4*)&A_[(size_t)kg * aRowStride + m0 + m];
            As[kk][m]     = tf(v.x);
            As[kk][m + 1] = tf(v.y);
            As[kk][m + 2] = tf(v.z);
            As[kk][m + 3] = tf(v.w);
        }
        if (taps == 1){
#pragma unroll
            for (int i = 0; i < 2; ++i){
                int qi = tid + i * 256;
                int kk = qi >> 5, col = (qi & 31) * 4;
                int kg = k0 + kk;
                float4 v = make_float4(0.f, 0.f, 0.f, 0.f);
                if (kg < Ktot)
                    v = *(const float4*)&Xb[(size_t)kg * xChanStride + n0 + col];
                Bs[kk][col]     = tf(v.x);
                Bs[kk][col + 1] = tf(v.y);
                Bs[kk][col + 2] = tf(v.z);
                Bs[kk][col + 3] = tf(v.w);
            }
        } else {
            int tapU = -1, kyU = 0, kxU = 0, krBase = 0;
            if ((K & 15) == 0){
                tapU = k0 / K; kyU = tapU / 3; kxU = tapU % 3; krBase = k0 - tapU * K;
            }
#pragma unroll
            for (int i = 0; i < 8; ++i){
                int idx = tid + i * 256;
                int kk = idx >> 7, col = idx & 127;
                int kg = k0 + kk;
                float v = 0.f;
                if (kg < Ktot){
                    int tap, kr, ky, kx;
                    if (tapU >= 0){ tap = tapU; kr = krBase + kk; ky = kyU; kx = kxU; }
                    else { tap = kg / K; kr = kg - tap * K; ky = tap / 3; kx = tap % 3; }
                    int n = n0 + col, yy = n >> 6, xx = n & 63;
                    v = Xb[(size_t)kr * xChanStride + (yy + ky) * PADW + xx + kx];
                }
                Bs[kk][col] = tf(v);
            }
        }
        __syncthreads();
#pragma unroll
        for (int ks = 0; ks < 16; ks += 8){
            uint32_t afr[4][4], bfr[4][2];
#pragma unroll
            for (int mi = 0; mi < 4; ++mi){
                int mb = warpM * 64 + mi * 16 + gid;
                afr[mi][0] = __float_as_uint(As[ks + tig][mb]);
                afr[mi][1] = __float_as_uint(As[ks + tig][mb + 8]);
                afr[mi][2] = __float_as_uint(As[ks + tig + 4][mb]);
                afr[mi][3] = __float_as_uint(As[ks + tig + 4][mb + 8]);
            }
#pragma unroll
            for (int ni = 0; ni < 4; ++ni){
                int nb = warpN * 32 + ni * 8 + gid;
                bfr[ni][0] = __float_as_uint(Bs[ks + tig][nb]);
                bfr[ni][1] = __float_as_uint(Bs[ks + tig + 4][nb]);
            }
#pragma unroll
            for (int mi = 0; mi < 4; ++mi)
#pragma unroll
                for (int ni = 0; ni < 4; ++ni)
                    mma_tf32(acc[mi][ni], afr[mi], bfr[ni]);
        }
        __syncthreads();
    }

    size_t cb = (size_t)b * cBatchStride;
#pragma unroll
    for (int mi = 0; mi < 4; ++mi)
#pragma unroll
        for (int ni = 0; ni < 4; ++ni)
#pragma unroll
            for (int p = 0; p < 4; ++p){
                int row = m0 + warpM * 64 + mi * 16 + gid + (p >> 1) * 8;
                if (row >= M) continue;
                int n   = n0 + warpN * 32 + ni * 8 + 2 * tig + (p & 1);
                float vv = acc[mi][ni][p] * scale + (bias ? bias[row] : 0.f);
                if (relu) vv = fmaxf(vv, 0.f);
                int yy = n >> 6, xx = n & 63;
                if (addsrc)
                    vv += addsrc[(size_t)b * addBatchStride + (size_t)row * PADN + (size_t)(yy + 1) * PADW + xx + 1];
                if (outPadded)
                    Cout[cb + (size_t)row * PADN + (size_t)(yy + 1) * PADW + xx + 1] = vv;
                else
                    Cout[cb + (size_t)row * NPIX + n] = vv;
            }
}

// ---------------- mask GEMM: split-tf32, block 128x128, warp 64x32 ----------------
__global__ __launch_bounds__(256, 1) void mask_split(
    const float* __restrict__ qp, const float* __restrict__ kp,
    unsigned char* __restrict__ mask)
{
    int b = blockIdx.z;
    int n0 = blockIdx.y * 128, m0 = blockIdx.x * 128;
    const float* Ap = qp + (size_t)b * DPCH * NPIX;
    const float* Bp = kp + (size_t)b * DPCH * NPIX;
    __shared__ float As[16][136];
    __shared__ float Bs[16][136];
    int tid = threadIdx.x;
    int wid = tid >> 5, lane = tid & 31;
    int gid = lane >> 2, tig = lane & 3;
    int warpM = wid & 1, warpN = wid >> 1;
    float acc[4][4][4];
#pragma unroll
    for (int mi = 0; mi < 4; ++mi)
#pragma unroll
        for (int ni = 0; ni < 4; ++ni)
#pragma unroll
            for (int p = 0; p < 4; ++p) acc[mi][ni][p] = 0.f;

    for (int k0 = 0; k0 < 192; k0 += 16){
        int seg = k0 >> 6;
        int krb = k0 & 63;
#pragma unroll
        for (int i = 0; i < 2; ++i){
            int qi = tid + i * 256;
            int kk = qi >> 5, m = (qi & 31) * 4;
            float4 v = *(const float4*)&Ap[(size_t)(krb + kk) * NPIX + n0 + m];
            float sv[4] = {v.x, v.y, v.z, v.w};
#pragma unroll
            for (int j = 0; j < 4; ++j){
                uint32_t hi = f2tf32(sv[j]);
                uint32_t o = hi;
                if (seg == 1){ float lo = sv[j] - __uint_as_float(hi); o = f2tf32(lo); }
                As[kk][m + j] = __uint_as_float(o);
            }
        }
#pragma unroll
        for (int i = 0; i < 2; ++i){
            int qi = tid + i * 256;
            int kk = qi >> 5, col = (qi & 31) * 4;
            float4 v = *(const float4*)&Bp[(size_t)(krb + kk) * NPIX + m0 + col];
            float sv[4] = {v.x, v.y, v.z, v.w};
#pragma unroll
            for (int j = 0; j < 4; ++j){
                uint32_t hi = f2tf32(sv[j]);
                uint32_t o = hi;
                if (seg == 2){ float lo = sv[j] - __uint_as_float(hi); o = f2tf32(lo); }
                Bs[kk][col + j] = __uint_as_float(o);
            }
        }
        __syncthreads();
#pragma unroll
        for (int ks = 0; ks < 16; ks += 8){
            uint32_t afr[4][4], bfr[4][2];
#pragma unroll
            for (int mi = 0; mi < 4; ++mi){
                int mb = warpM * 64 + mi * 16 + gid;
                afr[mi][0] = __float_as_uint(As[ks + tig][mb]);
                afr[mi][1] = __float_as_uint(As[ks + tig][mb + 8]);
                afr[mi][2] = __float_as_uint(As[ks + tig + 4][mb]);
                afr[mi][3] = __float_as_uint(As[ks + tig + 4][mb + 8]);
            }
#pragma unroll
            for (int ni = 0; ni < 4; ++ni){
                int nb = warpN * 32 + ni * 8 + gid;
                bfr[ni][0] = __float_as_uint(Bs[ks + tig][nb]);
                bfr[ni][1] = __float_as_uint(Bs[ks + tig + 4][nb]);
            }
#pragma unroll
            for (int mi = 0; mi < 4; ++mi)
#pragma unroll
                for (int ni = 0; ni < 4; ++ni)
                    mma_tf32(acc[mi][ni], afr[mi], bfr[ni]);
        }
        __syncthreads();
    }
    size_t base = (size_t)b * NPIX * NPIX;
#pragma unroll
    for (int mi = 0; mi < 4; ++mi)
#pragma unroll
        for (int ni = 0; ni < 4; ++ni)
#pragma unroll
            for (int p = 0; p < 4; ++p){
                int n = n0 + warpM * 64 + mi * 16 + gid + (p >> 1) * 8;
                int m = m0 + warpN * 32 + ni * 8 + 2 * tig + (p & 1);
                mask[base + (size_t)n * NPIX + m] = (acc[mi][ni][p] > 0.f) ? 1 : 0;
            }
}

// -------- per-row softmax stats (both variants) + conf, vectorized --------
__global__ __launch_bounds__(256) void row_stats(
    const float* __restrict__ cor, const unsigned char* __restrict__ mask,
    float* __restrict__ stats, float* __restrict__ conf)
{
    int b = blockIdx.y, n = blockIdx.x;
    const float* row = cor + ((size_t)b * NPIX + n) * NPIX;
    const unsigned char* mrow = mask + ((size_t)b * NPIX + n) * NPIX;
    int t = threadIdx.x;
    float m1 = -1e30f, m2 = -1e30f;
    for (int i = t * 4; i < NPIX; i += 1024){
        float4 s4 = *(const float4*)&row[i];
        unsigned int mk4 = *(const unsigned int*)&mrow[i];
        float sv[4] = {s4.x, s4.y, s4.z, s4.w};
#pragma unroll
        for (int j = 0; j < 4; ++j){
            m1 = fmaxf(m1, sv[j]);
            m2 = fmaxf(m2, ((mk4 >> (8 * j)) & 0xff) ? -10000.f : sv[j]);
        }
    }
    __shared__ float r1[256], r2[256], r3[256];
    r1[t] = m1; r2[t] = m2;
    __syncthreads();
    for (int o = 128; o > 0; o >>= 1){
        if (t < o){ r1[t] = fmaxf(r1[t], r1[t + o]); r2[t] = fmaxf(r2[t], r2[t + o]); }
        __syncthreads();
    }
    float M1 = r1[0], M2 = r2[0];
    __syncthreads();
    float d1 = 0.f, num = 0.f, d2 = 0.f;
    for (int i = t * 4; i < NPIX; i += 1024){
        float4 s4 = *(const float4*)&row[i];
        unsigned int mk4 = *(const unsigned int*)&mrow[i];
        float sv[4] = {s4.x, s4.y, s4.z, s4.w};
#pragma unroll
        for (int j = 0; j < 4; ++j){
            int mk = (mk4 >> (8 * j)) & 0xff;
            float e1 = fast_exp(sv[j] - M1);
            d1 += e1;
            num += mk ? e1 : 0.f;
            d2 += fast_exp((mk ? -10000.f : sv[j]) - M2);
        }
    }
    r1[t] = d1; r2[t] = num; r3[t] = d2;
    __syncthreads();
    for (int o = 128; o > 0; o >>= 1){
        if (t < o){ r1[t] += r1[t + o]; r2[t] += r2[t + o]; r3[t] += r3[t + o]; }
        __syncthreads();
    }
    if (t == 0){
        float* st = stats + ((size_t)b * NPIX + n) * 4;
        st[0] = M1; st[1] = r1[0]; st[2] = M2; st[3] = r3[0];
        conf[(size_t)b * NPIX + n] = r2[0] / r1[0];
    }
}

// -------- tensor attention: block 128n x 128c, warp 64x32 --------
// grid: (32, 4, BATCH); var = y>>1, c0 = (y&1)*128
__global__ __launch_bounds__(256, 1) void attn_tf32(
    const float* __restrict__ cor, const unsigned char* __restrict__ mask,
    const float* __restrict__ stats, const float* __restrict__ VT1,
    const float* __restrict__ VT2, float* __restrict__ out1, float* __restrict__ out2)
{
    int b = blockIdx.z;
    int var = blockIdx.y >> 1;
    int c0 = (blockIdx.y & 1) * 128;
    int n0 = blockIdx.x * 128;
    const float* VT = var ? VT2 : VT1;
    float* outp = var ? out2 : out1;
    __shared__ float Ps[16][136];
    __shared__ float Vs[16][136];
    int tid = threadIdx.x;
    int wid = tid >> 5, lane = tid & 31;
    int gid = lane >> 2, tig = lane & 3;
    int warpM = wid & 1, warpN = wid >> 1;

    int pr = tid & 127, half = tid >> 7;   // this thread builds P row n0+pr, k-range half*8..+7
    const float* st = stats + ((size_t)b * NPIX + n0 + pr) * 4;
    float Mv = var ? st[2] : st[0];
    float Dv = 1.f / (var ? st[3] : st[1]);

    const float* corb = cor + (size_t)b * NPIX * NPIX;
    const unsigned char* mb = mask + (size_t)b * NPIX * NPIX;
    const float* VTb = VT + (size_t)b * NPIX * CVCH;

    float acc[4][4][4];
#pragma unroll
    for (int mi = 0; mi < 4; ++mi)
#pragma unroll
        for (int ni = 0; ni < 4; ++ni)
#pragma unroll
            for (int p = 0; p < 4; ++p) acc[mi][ni][p] = 0.f;

    for (int m0 = 0; m0 < NPIX; m0 += 16){
        // P tile: 128 rows x 16 k, exp on the fly
        {
            size_t off = (size_t)(n0 + pr) * NPIX + m0 + half * 8;
            float4 s0 = *(const float4*)&corb[off];
            float4 s1 = *(const float4*)&corb[off + 4];
            uint2 mkp = *(const uint2*)&mb[off];
            float sv[8] = {s0.x, s0.y, s0.z, s0.w, s1.x, s1.y, s1.z, s1.w};
#pragma unroll
            for (int j = 0; j < 8; ++j){
                int mk = (j < 4 ? (mkp.x >> (8 * j)) : (mkp.y >> (8 * (j - 4)))) & 0xff;
                float p;
                if (var == 0) p = mk ? __expf(sv[j] - Mv) * Dv : 0.f;
                else          p = __expf((mk ? -10000.f : sv[j]) - Mv) * Dv;
                Ps[half * 8 + j][pr] = tf(p);
            }
        }
        // V tile: 16 m-rows x 128 c
#pragma unroll
        for (int i = 0; i < 2; ++i){
            int qi = tid + i * 256;
            int kk = qi >> 5, c = (qi & 31) * 4;
            float4 v4 = *(const float4*)&VTb[(size_t)(m0 + kk) * CVCH + c0 + c];
            Vs[kk][c]     = tf(v4.x);
            Vs[kk][c + 1] = tf(v4.y);
            Vs[kk][c + 2] = tf(v4.z);
            Vs[kk][c + 3] = tf(v4.w);
        }
        __syncthreads();
#pragma unroll
        for (int ks = 0; ks < 16; ks += 8){
            uint32_t afr[4][4], bfr[4][2];
#pragma unroll
            for (int mi = 0; mi < 4; ++mi){
                int mbx = warpM * 64 + mi * 16 + gid;
                afr[mi][0] = __float_as_uint(Ps[ks + tig][mbx]);
                afr[mi][1] = __float_as_uint(Ps[ks + tig][mbx + 8]);
                afr[mi][2] = __float_as_uint(Ps[ks + tig + 4][mbx]);
                afr[mi][3] = __float_as_uint(Ps[ks + tig + 4][mbx + 8]);
            }
#pragma unroll
            for (int ni = 0; ni < 4; ++ni){
                int nb = warpN * 32 + ni * 8 + gid;
                bfr[ni][0] = __float_as_uint(Vs[ks + tig][nb]);
                bfr[ni][1] = __float_as_uint(Vs[ks + tig + 4][nb]);
            }
#pragma unroll
            for (int mi = 0; mi < 4; ++mi)
#pragma unroll
                for (int ni = 0; ni < 4; ++ni)
                    mma_tf32(acc[mi][ni], afr[mi], bfr[ni]);
        }
        __syncthreads();
    }

    size_t obase = (size_t)b * CVCH * NPIX;
#pragma unroll
    for (int mi = 0; mi < 4; ++mi)
#pragma unroll
        for (int ni = 0; ni < 4; ++ni)
#pragma unroll
            for (int p = 0; p < 4; ++p){
                int n = n0 + warpM * 64 + mi * 16 + gid + (p >> 1) * 8;
                int c = c0 + warpN * 32 + ni * 8 + 2 * tig + (p & 1);
                outp[obase + (size_t)c * NPIX + n] = acc[mi][ni][p];
            }
}

// -------- instance-norm stats of q --------
__global__ void inorm_stats(const float* __restrict__ q, float* __restrict__ inst){
    int bc = blockIdx.x;
    const float* p = q + (size_t)bc * NPIX;
    int t = threadIdx.x;
    float s = 0.f, ss = 0.f;
    for (int i = t; i < NPIX; i += 256){ float v = p[i]; s += v; ss += v * v; }
    __shared__ float rs[256], rss[256];
    rs[t] = s; rss[t] = ss;
    __syncthreads();
    for (int o = 128; o > 0; o >>= 1){
        if (t < o){ rs[t] += rs[t + o]; rss[t] += rss[t + o]; }
        __syncthreads();
    }
    if (t == 0){
        float m = rs[0] / NPIX;
        float var = rss[0] / NPIX - m * m;
        inst[bc * 2] = m;
        inst[bc * 2 + 1] = rsqrtf(var + 1e-5f);
    }
}

// -------- fuse: ypre = out + (1-conf)*spade + q; pono stats --------
__global__ __launch_bounds__(256) void fuse1(
    const float* __restrict__ outb, const float* __restrict__ q,
    const float* __restrict__ gamma, const float* __restrict__ beta,
    const float* __restrict__ inst, const float* __restrict__ conf,
    float* __restrict__ ypre, float* __restrict__ pst)
{
    int b = blockIdx.x >> 6, y = blockIdx.x & 63;
    int tid = threadIdx.x;
    int x = tid & 63, cl = tid >> 6;
    int n = y * 64 + x;
    float one_m = 1.f - conf[(size_t)b * NPIX + n];
    size_t base = (size_t)b * CVCH * NPIX + n;
    float s = 0.f, ss = 0.f;
    for (int c = cl; c < CVCH; c += 4){
        size_t o = base + (size_t)c * NPIX;
        float qq = q[o];
        float im = inst[((size_t)b * CVCH + c) * 2];
        float is = inst[((size_t)b * CVCH + c) * 2 + 1];
        float sp = (qq - im) * is * (1.f + gamma[o]) + beta[o];
        float v = outb[o] + one_m * sp + qq;
        ypre[o] = v;
        s += v; ss += v * v;
    }
    __shared__ float rs[4][64], rss[4][64];
    rs[cl][x] = s; rss[cl][x] = ss;
    __syncthreads();
    if (cl == 0){
        float S  = rs[0][x] + rs[1][x] + rs[2][x] + rs[3][x];
        float SS = rss[0][x] + rss[1][x] + rss[2][x] + rss[3][x];
        float m = S / 256.f;
        float var = SS / 256.f - m * m;
        pst[((size_t)b * NPIX + n) * 2] = m;
        pst[((size_t)b * NPIX + n) * 2 + 1] = rsqrtf(var + 1e-5f);
    }
}

__global__ void fuse2(const float* __restrict__ ypre, const float* __restrict__ pst,
                      float* __restrict__ ypad){
    int idx = blockIdx.x * blockDim.x + threadIdx.x;
    if (idx >= BATCH * CVCH * NPIX) return;
    int n = idx & (NPIX - 1);
    int c = (idx >> 12) & 255;
    int b = idx >> 20;
    float m  = pst[((size_t)b * NPIX + n) * 2];
    float is = pst[((size_t)b * NPIX + n) * 2 + 1];
    int yy = n >> 6, xx = n & 63;
    ypad[(size_t)b * CVCH * PADN + (size_t)c * PADN + (size_t)(yy + 1) * PADW + xx + 1]
        = (ypre[idx] - m) * is;
}

extern "C" void kernel_launch(void* const* d_in, const int* in_sizes, int n_in,
                              void* d_out, int out_size){
    float* arena = nullptr;
    cudaGetSymbolAddress((void**)&arena, g_arena);

    const float* q    = (const float*)d_in[0];
    const float* k    = (const float*)d_in[1];
    const float* v    = (const float*)d_in[2];
    const float* pos  = (const float*)d_in[3];
    const float* v2   = (const float*)d_in[5];

    float* res  = (float*)d_out;
    float* out2 = res + (size_t)BATCH * CVCH * NPIX;
    float* cor  = out2 + (size_t)BATCH * CVCH * NPIX;

    float* QUERY = arena + OFF_QUERY;
    float* KEYT  = arena + OFF_KEYT;
    float* QF    = arena + OFF_QF;
    float* KF    = arena + OFF_KF;
    float* QP    = arena + OFF_QP;
    float* KP    = arena + OFF_KP;
    float* VH    = arena + OFF_VH;
    float* OUTB  = arena + OFF_OUT;
    float* STATS = arena + OFF_STATS;
    float* CONF  = arena + OFF_CONF;
    float* ACTV  = arena + OFF_ACTV;
    float* GAMMA = arena + OFF_GAMMA;
    float* BETA  = arena + OFF_BETA;
    float* INST  = arena + OFF_INST;
    float* YPRE  = arena + OFF_YPRE;
    float* PST   = arena + OFF_PST;
    float* YPAD  = arena + OFF_YPAD;
    float* T1PAD = arena + OFF_T1PAD;
    float* SEGP  = arena + OFF_SEGP;
    float* VHT   = arena + OFF_VHT;
    float* V2T   = arena + OFF_V2T;
    float* WT    = arena + OFF_WT;
    unsigned char* MASK = (unsigned char*)(arena + OFF_MASK);

    auto T = [&](int si, size_t off, int M, int K, int taps){
        int tot = M * K * taps;
        transpose_w<<<(tot + 255) / 256, 256>>>((const float*)d_in[si], WT + off, M, K, taps);
    };

    long sQK = (long)CQKCH * NPIX, sCV = (long)CVCH * NPIX, sDP = (long)DPCH * NPIX;
    long sCOR = (long)NPIX * NPIX;

    T(6,  WT_F,   320, 320, 1);
    T(8,  WT_G,   320, 320, 1);
    pad_seg<<<(BATCH * 3 * PADN + 255) / 256, 256>>>((const float*)d_in[4], SEGP);
    norm_concat<<<dim3(BATCH * 64, 2), 256>>>(q, k, pos, QUERY, KEYT);
    T(10, WT_H,   256, 256, 1);
    gemm_tf32<<<dim3(32, 3, 2), 256>>>(WT + WT_F,  0, 320, 320, QUERY, sQK, NPIX,
        (const float*)d_in[7],  QF, sQK, 320, 1, 0, 0, 1.f, nullptr, 0);
    gemm_tf32<<<dim3(32, 3, 2), 256>>>(WT + WT_G,  0, 320, 320, KEYT,  sQK, NPIX,
        (const float*)d_in[9],  KF, sQK, 320, 1, 0, 0, 1.f, nullptr, 0);
    gemm_tf32<<<dim3(32, 2, 2), 256>>>(WT + WT_H,  0, 256, 256, v,     sCV, NPIX,
        (const float*)d_in[11], VH, sCV, 256, 1, 0, 0, 1.f, nullptr, 0);

    T(12, WT_FP,  64,  320, 1);
    T(14, WT_GP,  64,  320, 1);
    gemm_wx_f32<<<dim3(64, 1, 2), 256>>>(WT + WT_FP, QUERY, (const float*)d_in[13],
        QP, 64, 320, sQK, NPIX, sDP);
    gemm_wx_f32<<<dim3(64, 1, 2), 256>>>(WT + WT_GP, KEYT,  (const float*)d_in[15],
        KP, 64, 320, sQK, NPIX, sDP);

    T(16, WT_SPS, 128, 3,   9);
    T(18, WT_SPG, 256, 128, 9);
    T(20, WT_SPB, 256, 128, 9);
    T(22, WT_R1,  256, 256, 9);
    T(24, WT_R2,  256, 256, 9);

    // cor = (QF^T KF) / sqrt(320)
    gemm_tf32<<<dim3(32, 32, 2), 256>>>(QF, sQK, NPIX, 4096, KF, sQK, NPIX,
        nullptr, cor, sCOR, 320, 1, 0, 0, 0.0559016994f, nullptr, 0);
    // mask: split-tf32 on tensor pipe
    mask_split<<<dim3(32, 32, 2), 256>>>(QP, KP, MASK);

    row_stats<<<dim3(NPIX, BATCH), 256>>>(cor, MASK, STATS, CONF);

    transpose_cm<<<dim3(128, 8, 2), 256>>>(VH, VHT);
    transpose_cm<<<dim3(128, 8, 2), 256>>>(v2, V2T);

    attn_tf32<<<dim3(32, 4, 2), 256>>>(cor, MASK, STATS, VHT, V2T, OUTB, out2);

    // SPADE path
    int nACTV = BATCH * NHID * PADN, nPAD = BATCH * CVCH * PADN;
    zero_kernel<<<(nACTV + 255) / 256, 256>>>(ACTV, nACTV);
    zero_kernel<<<(nPAD + 255) / 256, 256>>>(YPAD, nPAD);
    zero_kernel<<<(nPAD + 255) / 256, 256>>>(T1PAD, nPAD);

    gemm_tf32<<<dim3(32, 1, 2), 256>>>(WT + WT_SPS, 0, 128, 128, SEGP, (long)3 * PADN, PADN,
        (const float*)d_in[17], ACTV, (long)NHID * PADN, 3, 9, 1, 1, 1.f, nullptr, 0);
    gemm_tf32<<<dim3(32, 2, 2), 256>>>(WT + WT_SPG, 0, 256, 256, ACTV, (long)NHID * PADN, PADN,
        (const float*)d_in[19], GAMMA, sCV, 128, 9, 0, 0, 1.f, nullptr, 0);
    gemm_tf32<<<dim3(32, 2, 2), 256>>>(WT + WT_SPB, 0, 256, 256, ACTV, (long)NHID * PADN, PADN,
        (const float*)d_in[21], BETA, sCV, 128, 9, 0, 0, 1.f, nullptr, 0);

    inorm_stats<<<BATCH * CVCH, 256>>>(q, INST);
    fuse1<<<BATCH * 64, 256>>>(OUTB, q, GAMMA, BETA, INST, CONF, YPRE, PST);
    fuse2<<<(BATCH * CVCH * NPIX + 255) / 256, 256>>>(YPRE, PST, YPAD);

    gemm_tf32<<<dim3(32, 2, 2), 256>>>(WT + WT_R1, 0, 256, 256, YPAD, (long)CVCH * PADN, PADN,
        (const float*)d_in[23], T1PAD, (long)CVCH * PADN, 256, 9, 1, 1, 1.f, nullptr, 0);
    gemm_tf32<<<dim3(32, 2, 2), 256>>>(WT + WT_R2, 0, 256, 256, T1PAD, (long)CVCH * PADN, PADN,
        (const float*)d_in[25], res, sCV, 256, 9, 0, 0, 1.f, YPAD, (long)CVCH * PADN);
}

// round 13
// speedup vs baseline: 1.2793x; 1.2793x over previous
#include <cuda_runtime.h>
#include <math.h>
#include <stdint.h>

#define NPIX 4096
#define PADW 66
#define PADN 4356
#define BATCH 2
#define CVCH 256
#define CQKCH 320
#define DPCH 64
#define NHID 128

// ---------------- scratch arena ----------------
constexpr size_t SZ_QK = (size_t)BATCH * CQKCH * NPIX;
constexpr size_t SZ_CV = (size_t)BATCH * CVCH * NPIX;
constexpr size_t SZ_DP = (size_t)BATCH * DPCH * NPIX;

constexpr size_t OFF_QUERY = 0;
constexpr size_t OFF_KEYT  = OFF_QUERY + SZ_QK;
constexpr size_t OFF_QF    = OFF_KEYT + SZ_QK;
constexpr size_t OFF_KF    = OFF_QF + SZ_QK;
constexpr size_t OFF_QP    = OFF_KF + SZ_QK;
constexpr size_t OFF_KP    = OFF_QP + SZ_DP;
constexpr size_t OFF_VH    = OFF_KP + SZ_DP;
constexpr size_t OFF_OUT   = OFF_VH + SZ_CV;
constexpr size_t OFF_STATS = OFF_OUT + SZ_CV;
constexpr size_t OFF_CONF  = OFF_STATS + (size_t)BATCH*NPIX*4;
constexpr size_t OFF_ACTV  = OFF_CONF + (size_t)BATCH*NPIX;
constexpr size_t OFF_GAMMA = OFF_ACTV + (size_t)BATCH*NHID*PADN;
constexpr size_t OFF_BETA  = OFF_GAMMA + SZ_CV;
constexpr size_t OFF_INST  = OFF_BETA + SZ_CV;
constexpr size_t OFF_YPRE  = OFF_INST + (size_t)BATCH*CVCH*2;
constexpr size_t OFF_PST   = OFF_YPRE + SZ_CV;
constexpr size_t OFF_YPAD  = OFF_PST + (size_t)BATCH*NPIX*2;
constexpr size_t OFF_T1PAD = OFF_YPAD + (size_t)BATCH*CVCH*PADN;
constexpr size_t OFF_SEGP  = OFF_T1PAD + (size_t)BATCH*CVCH*PADN;
constexpr size_t OFF_VHT   = OFF_SEGP + 26176;
constexpr size_t OFF_V2T   = OFF_VHT + SZ_CV;
constexpr size_t OFF_WT    = OFF_V2T + SZ_CV;
constexpr size_t WT_F   = 0;
constexpr size_t WT_G   = WT_F  + 320*320;
constexpr size_t WT_H   = WT_G  + 320*320;
constexpr size_t WT_FP  = WT_H  + 256*256;
constexpr size_t WT_GP  = WT_FP + 320*64;
constexpr size_t WT_SPS = WT_GP + 320*64;
constexpr size_t WT_SPG = WT_SPS + 9*3*128;
constexpr size_t WT_SPB = WT_SPG + 9*128*256;
constexpr size_t WT_R1  = WT_SPB + 9*128*256;
constexpr size_t WT_R2  = WT_R1  + 9*256*256;
constexpr size_t WT_END = WT_R2  + 9*256*256;
constexpr size_t OFF_MASK = OFF_WT + ((WT_END + 63) & ~(size_t)63);
constexpr size_t ARENA_FLOATS = OFF_MASK + ((size_t)BATCH*NPIX*NPIX)/4 + 64;

__device__ __align__(16) float g_arena[ARENA_FLOATS];

// ---------------- helpers ----------------
__device__ __forceinline__ uint32_t f2tf32(float v){
    uint32_t r;
    asm("cvt.rna.tf32.f32 %0, %1;" : "=r"(r) : "f"(v));
    return r;
}
__device__ __forceinline__ float tf(float v){ return __uint_as_float(f2tf32(v)); }

__device__ __forceinline__ void mma_tf32(float* d, const uint32_t* a, const uint32_t* b){
    asm volatile("mma.sync.aligned.m16n8k8.row.col.f32.tf32.tf32.f32 "
        "{%0,%1,%2,%3}, {%4,%5,%6,%7}, {%8,%9}, {%0,%1,%2,%3};"
        : "+f"(d[0]), "+f"(d[1]), "+f"(d[2]), "+f"(d[3])
        : "r"(a[0]), "r"(a[1]), "r"(a[2]), "r"(a[3]), "r"(b[0]), "r"(b[1]));
}

__device__ __forceinline__ float fast_exp(float x){
    float t = x * 1.4426950408889634f;
    t = fmaxf(t, -126.0f);
    float tr = t + 12582912.0f;
    int   k  = __float_as_int(tr) - 0x4B400000;
    float fi = tr - 12582912.0f;
    float f  = t - fi;
    float p = 1.0f + f*(0.6931471805599453f + f*(0.2402265069591007f
              + f*(0.0555041086648216f + f*0.0096181291076285f)));
    return p * __int_as_float((k + 127) << 23);
}

// ---------------- utility kernels ----------------
__global__ void zero_kernel(float* p, int n){
    int i = blockIdx.x * blockDim.x + threadIdx.x;
    if (i < n) p[i] = 0.f;
}

// dst[t*K*M + k*M + m] = src[(m*K+k)*taps + t]; optionally tf32-rounded
__global__ void transpose_w(const float* __restrict__ src, float* __restrict__ dst,
                            int M, int K, int taps, int rnd){
    int idx = blockIdx.x * blockDim.x + threadIdx.x;
    if (idx >= M * K * taps) return;
    int t = idx / (K * M);
    int r = idx % (K * M);
    int k = r / M;
    int m = r % M;
    float v = src[((size_t)m * K + k) * taps + t];
    dst[idx] = rnd ? tf(v) : v;
}

// [b][c][m] -> [b][m][c], tf32-rounded (feeds attention V operand)
__global__ __launch_bounds__(256) void transpose_cm(const float* __restrict__ src,
                                                    float* __restrict__ dst){
    __shared__ float s[32][33];
    int mBase = blockIdx.x * 32, cBase = blockIdx.y * 32, b = blockIdx.z;
    int tx = threadIdx.x & 31, ty = threadIdx.x >> 5;
    size_t base = (size_t)b * CVCH * NPIX;
#pragma unroll
    for (int i = 0; i < 4; ++i){
        int c = cBase + ty + i * 8;
        s[ty + i * 8][tx] = src[base + (size_t)c * NPIX + mBase + tx];
    }
    __syncthreads();
#pragma unroll
    for (int i = 0; i < 4; ++i){
        int m = mBase + ty + i * 8;
        dst[base + (size_t)m * CVCH + cBase + tx] = tf(s[tx][ty + i * 8]);
    }
}

__global__ void pad_seg(const float* __restrict__ seg, float* __restrict__ dst){
    int idx = blockIdx.x * blockDim.x + threadIdx.x;
    if (idx >= BATCH * 3 * PADN) return;
    int bc = idx / PADN;
    int r = idx % PADN;
    int yy = r / PADW, xx = r % PADW;
    float v = 0.f;
    if (yy >= 1 && yy <= 64 && xx >= 1 && xx <= 64)
        v = seg[(size_t)bc * NPIX + (yy - 1) * 64 + (xx - 1)];
    dst[idx] = tf(v);
}

__global__ __launch_bounds__(256) void norm_concat(
    const float* __restrict__ q, const float* __restrict__ k,
    const float* __restrict__ pos, float* __restrict__ outq, float* __restrict__ outk){
    const float* src = blockIdx.y ? k : q;
    float* dst = blockIdx.y ? outk : outq;
    int b = blockIdx.x / 64, y = blockIdx.x % 64;
    int tid = threadIdx.x;
    int x = tid & 63, cl = tid >> 6;
    const float* sb = src + (size_t)b * CVCH * NPIX + y * 64;
    __shared__ float partial[4][64];
    __shared__ float inv[64];
    float ss = 0.f;
    for (int c = cl; c < CVCH; c += 4){ float v = sb[(size_t)c * NPIX + x]; ss += v * v; }
    partial[cl][x] = ss;
    __syncthreads();
    if (cl == 0){
        float s = partial[0][x] + partial[1][x] + partial[2][x] + partial[3][x];
        inv[x] = 1.f / (sqrtf(s) + 2.220446049250313e-16f);
    }
    __syncthreads();
    float* db = dst + (size_t)b * CQKCH * NPIX + y * 64;
    float iv = inv[x];
    for (int c = cl; c < CVCH; c += 4) db[(size_t)c * NPIX + x] = sb[(size_t)c * NPIX + x] * iv;
    const float* pb = pos + y * 64;
    for (int i = tid; i < 64 * 64; i += 256){
        int cp = i >> 6, xx = i & 63;
        db[(size_t)(CVCH + cp) * NPIX + xx] = pb[(size_t)cp * NPIX + xx];
    }
}

// ------------- exact-fp32 1x1 conv GEMM (QP/KP — mask sign sensitivity) -------------
__global__ __launch_bounds__(256) void gemm_wx_f32(
    const float* __restrict__ Wt, const float* __restrict__ X,
    const float* __restrict__ bias, float* __restrict__ Cout,
    int M, int K, long xBatchStride, int xChanStride, long cBatchStride)
{
    int b = blockIdx.z;
    int n0 = blockIdx.x * 64;
    int m0 = blockIdx.y * 64;
    const float* Xb = X + (size_t)b * xBatchStride;
    __shared__ __align__(16) float As[16][64];
    __shared__ __align__(16) float Bs[16][64];
    float acc[4][4] = {};
    int tid = threadIdx.x;
    int tx = tid & 15, ty = tid >> 4;
    for (int k0 = 0; k0 < K; k0 += 16){
#pragma unroll
        for (int i = 0; i < 4; ++i){
            int idx = tid + 256 * i;
            int kk = idx >> 6, col = idx & 63;
            int kg = k0 + kk;
            As[kk][col] = (kg < K) ? Wt[(size_t)kg * M + m0 + col] : 0.f;
            Bs[kk][col] = (kg < K) ? Xb[(size_t)kg * xChanStride + n0 + col] : 0.f;
        }
        __syncthreads();
#pragma unroll
        for (int kk = 0; kk < 16; ++kk){
            float4 a  = *(const float4*)&As[kk][ty * 4];
            float4 bb = *(const float4*)&Bs[kk][tx * 4];
            float av[4] = {a.x, a.y, a.z, a.w};
            float bv[4] = {bb.x, bb.y, bb.z, bb.w};
#pragma unroll
            for (int i = 0; i < 4; ++i)
#pragma unroll
                for (int j = 0; j < 4; ++j)
                    acc[i][j] += av[i] * bv[j];
        }
        __syncthreads();
    }
#pragma unroll
    for (int i = 0; i < 4; ++i){
        int m = m0 + ty * 4 + i;
        float bvv = bias ? bias[m] : 0.f;
#pragma unroll
        for (int j = 0; j < 4; ++j)
            Cout[(size_t)b * cBatchStride + (size_t)m * NPIX + n0 + tx * 4 + j] = acc[i][j] + bvv;
    }
}

// ------------- tf32 tensor GEMM: block 128Mx128N, warp 64x32, 2 CTAs/SM -------------
template<bool CVTB>
__global__ __launch_bounds__(256, 2) void gemm_tf32(
    const float* __restrict__ A, long aBatchStride, int aRowStride, int M,
    const float* __restrict__ X, long xBatchStride, int xChanStride,
    const float* __restrict__ bias, float* __restrict__ Cout, long cBatchStride,
    int K, int taps, int relu, int outPadded, float scale, int roundOut,
    const float* __restrict__ addsrc, long addBatchStride)
{
    int b = blockIdx.z;
    int n0 = blockIdx.x * 128;
    int m0 = blockIdx.y * 128;
    const float* A_ = A + (size_t)b * aBatchStride;
    const float* Xb = X + (size_t)b * xBatchStride;
    __shared__ float As[16][136];
    __shared__ float Bs[16][136];
    int tid = threadIdx.x;
    int wid = tid >> 5, lane = tid & 31;
    int gid = lane >> 2, tig = lane & 3;
    int warpM = wid & 1, warpN = wid >> 1;
    float acc[4][4][4];
#pragma unroll
    for (int mi = 0; mi < 4; ++mi)
#pragma unroll
        for (int ni = 0; ni < 4; ++ni)
#pragma unroll
            for (int p = 0; p < 4; ++p) acc[mi][ni][p] = 0.f;

    int Ktot = K * taps;
    for (int k0 = 0; k0 < Ktot; k0 += 16){
        // A: 128 wide, 2 float4 per thread (pre-rounded producers -> no cvt)
#pragma unroll
        for (int i = 0; i < 2; ++i){
            int qi = tid + i * 256;
            int kk = qi >> 5, m = (qi & 31) * 4;
            int kg = k0 + kk;
            float4 v = make_float4(0.f, 0.f, 0.f, 0.f);
            if (kg < Ktot && m0 + m < M)
                v = *(const float4*)&A_[(size_t)kg * aRowStride + m0 + m];
            As[kk][m]     = v.x;
            As[kk][m + 1] = v.y;
            As[kk][m + 2] = v.z;
            As[kk][m + 3] = v.w;
        }
        if (taps == 1){
#pragma unroll
            for (int i = 0; i < 2; ++i){
                int qi = tid + i * 256;
                int kk = qi >> 5, col = (qi & 31) * 4;
                int kg = k0 + kk;
                float4 v = make_float4(0.f, 0.f, 0.f, 0.f);
                if (kg < Ktot)
                    v = *(const float4*)&Xb[(size_t)kg * xChanStride + n0 + col];
                if (CVTB){
                    Bs[kk][col]     = tf(v.x);
                    Bs[kk][col + 1] = tf(v.y);
                    Bs[kk][col + 2] = tf(v.z);
                    Bs[kk][col + 3] = tf(v.w);
                } else {
                    Bs[kk][col]     = v.x;
                    Bs[kk][col + 1] = v.y;
                    Bs[kk][col + 2] = v.z;
                    Bs[kk][col + 3] = v.w;
                }
            }
        } else {
            int tapU = -1, kyU = 0, kxU = 0, krBase = 0;
            if ((K & 15) == 0){
                tapU = k0 / K; kyU = tapU / 3; kxU = tapU % 3; krBase = k0 - tapU * K;
            }
#pragma unroll
            for (int i = 0; i < 8; ++i){
                int idx = tid + i * 256;
                int kk = idx >> 7, col = idx & 127;
                int kg = k0 + kk;
                float v = 0.f;
                if (kg < Ktot){
                    int tap, kr, ky, kx;
                    if (tapU >= 0){ tap = tapU; kr = krBase + kk; ky = kyU; kx = kxU; }
                    else { tap = kg / K; kr = kg - tap * K; ky = tap / 3; kx = tap % 3; }
                    int n = n0 + col, yy = n >> 6, xx = n & 63;
                    v = Xb[(size_t)kr * xChanStride + (yy + ky) * PADW + xx + kx];
                }
                Bs[kk][col] = CVTB ? tf(v) : v;
            }
        }
        __syncthreads();
#pragma unroll
        for (int ks = 0; ks < 16; ks += 8){
            uint32_t afr[4][4], bfr[4][2];
#pragma unroll
            for (int mi = 0; mi < 4; ++mi){
                int mb = warpM * 64 + mi * 16 + gid;
                afr[mi][0] = __float_as_uint(As[ks + tig][mb]);
                afr[mi][1] = __float_as_uint(As[ks + tig][mb + 8]);
                afr[mi][2] = __float_as_uint(As[ks + tig + 4][mb]);
                afr[mi][3] = __float_as_uint(As[ks + tig + 4][mb + 8]);
            }
#pragma unroll
            for (int ni = 0; ni < 4; ++ni){
                int nb = warpN * 32 + ni * 8 + gid;
                bfr[ni][0] = __float_as_uint(Bs[ks + tig][nb]);
                bfr[ni][1] = __float_as_uint(Bs[ks + tig + 4][nb]);
            }
#pragma unroll
            for (int mi = 0; mi < 4; ++mi)
#pragma unroll
                for (int ni = 0; ni < 4; ++ni)
                    mma_tf32(acc[mi][ni], afr[mi], bfr[ni]);
        }
        __syncthreads();
    }

    size_t cb = (size_t)b * cBatchStride;
#pragma unroll
    for (int mi = 0; mi < 4; ++mi)
#pragma unroll
        for (int ni = 0; ni < 4; ++ni)
#pragma unroll
            for (int p = 0; p < 4; ++p){
                int row = m0 + warpM * 64 + mi * 16 + gid + (p >> 1) * 8;
                if (row >= M) continue;
                int n   = n0 + warpN * 32 + ni * 8 + 2 * tig + (p & 1);
                float vv = acc[mi][ni][p] * scale + (bias ? bias[row] : 0.f);
                if (relu) vv = fmaxf(vv, 0.f);
                if (roundOut) vv = tf(vv);
                int yy = n >> 6, xx = n & 63;
                if (addsrc)
                    vv += addsrc[(size_t)b * addBatchStride + (size_t)row * PADN + (size_t)(yy + 1) * PADW + xx + 1];
                if (outPadded)
                    Cout[cb + (size_t)row * PADN + (size_t)(yy + 1) * PADW + xx + 1] = vv;
                else
                    Cout[cb + (size_t)row * NPIX + n] = vv;
            }
}

// ---------------- mask GEMM: split-tf32, block 128x128, warp 64x32 ----------------
__global__ __launch_bounds__(256, 2) void mask_split(
    const float* __restrict__ qp, const float* __restrict__ kp,
    unsigned char* __restrict__ mask)
{
    int b = blockIdx.z;
    int n0 = blockIdx.y * 128, m0 = blockIdx.x * 128;
    const float* Ap = qp + (size_t)b * DPCH * NPIX;
    const float* Bp = kp + (size_t)b * DPCH * NPIX;
    __shared__ float As[16][136];
    __shared__ float Bs[16][136];
    int tid = threadIdx.x;
    int wid = tid >> 5, lane = tid & 31;
    int gid = lane >> 2, tig = lane & 3;
    int warpM = wid & 1, warpN = wid >> 1;
    float acc[4][4][4];
#pragma unroll
    for (int mi = 0; mi < 4; ++mi)
#pragma unroll
        for (int ni = 0; ni < 4; ++ni)
#pragma unroll
            for (int p = 0; p < 4; ++p) acc[mi][ni][p] = 0.f;

    for (int k0 = 0; k0 < 192; k0 += 16){
        int seg = k0 >> 6;
        int krb = k0 & 63;
#pragma unroll
        for (int i = 0; i < 2; ++i){
            int qi = tid + i * 256;
            int kk = qi >> 5, m = (qi & 31) * 4;
            float4 v = *(const float4*)&Ap[(size_t)(krb + kk) * NPIX + n0 + m];
            float sv[4] = {v.x, v.y, v.z, v.w};
#pragma unroll
            for (int j = 0; j < 4; ++j){
                uint32_t hi = f2tf32(sv[j]);
                uint32_t o = hi;
                if (seg == 1){ float lo = sv[j] - __uint_as_float(hi); o = f2tf32(lo); }
                As[kk][m + j] = __uint_as_float(o);
            }
        }
#pragma unroll
        for (int i = 0; i < 2; ++i){
            int qi = tid + i * 256;
            int kk = qi >> 5, col = (qi & 31) * 4;
            float4 v = *(const float4*)&Bp[(size_t)(krb + kk) * NPIX + m0 + col];
            float sv[4] = {v.x, v.y, v.z, v.w};
#pragma unroll
            for (int j = 0; j < 4; ++j){
                uint32_t hi = f2tf32(sv[j]);
                uint32_t o = hi;
                if (seg == 2){ float lo = sv[j] - __uint_as_float(hi); o = f2tf32(lo); }
                Bs[kk][col + j] = __uint_as_float(o);
            }
        }
        __syncthreads();
#pragma unroll
        for (int ks = 0; ks < 16; ks += 8){
            uint32_t afr[4][4], bfr[4][2];
#pragma unroll
            for (int mi = 0; mi < 4; ++mi){
                int mb = warpM * 64 + mi * 16 + gid;
                afr[mi][0] = __float_as_uint(As[ks + tig][mb]);
                afr[mi][1] = __float_as_uint(As[ks + tig][mb + 8]);
                afr[mi][2] = __float_as_uint(As[ks + tig + 4][mb]);
                afr[mi][3] = __float_as_uint(As[ks + tig + 4][mb + 8]);
            }
#pragma unroll
            for (int ni = 0; ni < 4; ++ni){
                int nb = warpN * 32 + ni * 8 + gid;
                bfr[ni][0] = __float_as_uint(Bs[ks + tig][nb]);
                bfr[ni][1] = __float_as_uint(Bs[ks + tig + 4][nb]);
            }
#pragma unroll
            for (int mi = 0; mi < 4; ++mi)
#pragma unroll
                for (int ni = 0; ni < 4; ++ni)
                    mma_tf32(acc[mi][ni], afr[mi], bfr[ni]);
        }
        __syncthreads();
    }
    size_t base = (size_t)b * NPIX * NPIX;
#pragma unroll
    for (int mi = 0; mi < 4; ++mi)
#pragma unroll
        for (int ni = 0; ni < 4; ++ni)
#pragma unroll
            for (int p = 0; p < 4; ++p){
                int n = n0 + warpM * 64 + mi * 16 + gid + (p >> 1) * 8;
                int m = m0 + warpN * 32 + ni * 8 + 2 * tig + (p & 1);
                mask[base + (size_t)n * NPIX + m] = (acc[mi][ni][p] > 0.f) ? 1 : 0;
            }
}

// -------- per-row softmax stats (both variants) + conf, vectorized --------
__global__ __launch_bounds__(256) void row_stats(
    const float* __restrict__ cor, const unsigned char* __restrict__ mask,
    float* __restrict__ stats, float* __restrict__ conf)
{
    int b = blockIdx.y, n = blockIdx.x;
    const float* row = cor + ((size_t)b * NPIX + n) * NPIX;
    const unsigned char* mrow = mask + ((size_t)b * NPIX + n) * NPIX;
    int t = threadIdx.x;
    float m1 = -1e30f, m2 = -1e30f;
    for (int i = t * 4; i < NPIX; i += 1024){
        float4 s4 = *(const float4*)&row[i];
        unsigned int mk4 = *(const unsigned int*)&mrow[i];
        float sv[4] = {s4.x, s4.y, s4.z, s4.w};
#pragma unroll
        for (int j = 0; j < 4; ++j){
            m1 = fmaxf(m1, sv[j]);
            m2 = fmaxf(m2, ((mk4 >> (8 * j)) & 0xff) ? -10000.f : sv[j]);
        }
    }
    __shared__ float r1[256], r2[256], r3[256];
    r1[t] = m1; r2[t] = m2;
    __syncthreads();
    for (int o = 128; o > 0; o >>= 1){
        if (t < o){ r1[t] = fmaxf(r1[t], r1[t + o]); r2[t] = fmaxf(r2[t], r2[t + o]); }
        __syncthreads();
    }
    float M1 = r1[0], M2 = r2[0];
    __syncthreads();
    float d1 = 0.f, num = 0.f, d2 = 0.f;
    for (int i = t * 4; i < NPIX; i += 1024){
        float4 s4 = *(const float4*)&row[i];
        unsigned int mk4 = *(const unsigned int*)&mrow[i];
        float sv[4] = {s4.x, s4.y, s4.z, s4.w};
#pragma unroll
        for (int j = 0; j < 4; ++j){
            int mk = (mk4 >> (8 * j)) & 0xff;
            float e1 = fast_exp(sv[j] - M1);
            d1 += e1;
            num += mk ? e1 : 0.f;
            d2 += fast_exp((mk ? -10000.f : sv[j]) - M2);
        }
    }
    r1[t] = d1; r2[t] = num; r3[t] = d2;
    __syncthreads();
    for (int o = 128; o > 0; o >>= 1){
        if (t < o){ r1[t] += r1[t + o]; r2[t] += r2[t + o]; r3[t] += r3[t + o]; }
        __syncthreads();
    }
    if (t == 0){
        float* st = stats + ((size_t)b * NPIX + n) * 4;
        st[0] = M1; st[1] = r1[0]; st[2] = M2; st[3] = r3[0];
        conf[(size_t)b * NPIX + n] = r2[0] / r1[0];
    }
}

// -------- tensor attention: block 128n x 128c, warp 64x32, 2 CTAs/SM --------
// grid: (32, 4, BATCH); var = y>>1, c0 = (y&1)*128
__global__ __launch_bounds__(256, 2) void attn_tf32(
    const float* __restrict__ cor, const unsigned char* __restrict__ mask,
    const float* __restrict__ stats, const float* __restrict__ VT1,
    const float* __restrict__ VT2, float* __restrict__ out1, float* __restrict__ out2)
{
    int b = blockIdx.z;
    int var = blockIdx.y >> 1;
    int c0 = (blockIdx.y & 1) * 128;
    int n0 = blockIdx.x * 128;
    const float* VT = var ? VT2 : VT1;
    float* outp = var ? out2 : out1;
    __shared__ float Ps[16][136];
    __shared__ float Vs[16][136];
    int tid = threadIdx.x;
    int wid = tid >> 5, lane = tid & 31;
    int gid = lane >> 2, tig = lane & 3;
    int warpM = wid & 1, warpN = wid >> 1;

    int pr = tid & 127, half = tid >> 7;
    const float* st = stats + ((size_t)b * NPIX + n0 + pr) * 4;
    float Mv = var ? st[2] : st[0];
    float Dv = 1.f / (var ? st[3] : st[1]);

    const float* corb = cor + (size_t)b * NPIX * NPIX;
    const unsigned char* mb = mask + (size_t)b * NPIX * NPIX;
    const float* VTb = VT + (size_t)b * NPIX * CVCH;

    float acc[4][4][4];
#pragma unroll
    for (int mi = 0; mi < 4; ++mi)
#pragma unroll
        for (int ni = 0; ni < 4; ++ni)
#pragma unroll
            for (int p = 0; p < 4; ++p) acc[mi][ni][p] = 0.f;

    for (int m0 = 0; m0 < NPIX; m0 += 16){
        // P tile: 128 rows x 16 k, exp on the fly
        {
            size_t off = (size_t)(n0 + pr) * NPIX + m0 + half * 8;
            float4 s0 = *(const float4*)&corb[off];
            float4 s1 = *(const float4*)&corb[off + 4];
            uint2 mkp = *(const uint2*)&mb[off];
            float sv[8] = {s0.x, s0.y, s0.z, s0.w, s1.x, s1.y, s1.z, s1.w};
#pragma unroll
            for (int j = 0; j < 8; ++j){
                int mk = (j < 4 ? (mkp.x >> (8 * j)) : (mkp.y >> (8 * (j - 4)))) & 0xff;
                float p;
                if (var == 0) p = mk ? __expf(sv[j] - Mv) * Dv : 0.f;
                else          p = __expf((mk ? -10000.f : sv[j]) - Mv) * Dv;
                Ps[half * 8 + j][pr] = tf(p);
            }
        }
        // V tile: 16 m-rows x 128 c (VT pre-rounded -> no cvt)
#pragma unroll
        for (int i = 0; i < 2; ++i){
            int qi = tid + i * 256;
            int kk = qi >> 5, c = (qi & 31) * 4;
            float4 v4 = *(const float4*)&VTb[(size_t)(m0 + kk) * CVCH + c0 + c];
            Vs[kk][c]     = v4.x;
            Vs[kk][c + 1] = v4.y;
            Vs[kk][c + 2] = v4.z;
            Vs[kk][c + 3] = v4.w;
        }
        __syncthreads();
#pragma unroll
        for (int ks = 0; ks < 16; ks += 8){
            uint32_t afr[4][4], bfr[4][2];
#pragma unroll
            for (int mi = 0; mi < 4; ++mi){
                int mbx = warpM * 64 + mi * 16 + gid;
                afr[mi][0] = __float_as_uint(Ps[ks + tig][mbx]);
                afr[mi][1] = __float_as_uint(Ps[ks + tig][mbx + 8]);
                afr[mi][2] = __float_as_uint(Ps[ks + tig + 4][mbx]);
                afr[mi][3] = __float_as_uint(Ps[ks + tig + 4][mbx + 8]);
            }
#pragma unroll
            for (int ni = 0; ni < 4; ++ni){
                int nb = warpN * 32 + ni * 8 + gid;
                bfr[ni][0] = __float_as_uint(Vs[ks + tig][nb]);
                bfr[ni][1] = __float_as_uint(Vs[ks + tig + 4][nb]);
            }
#pragma unroll
            for (int mi = 0; mi < 4; ++mi)
#pragma unroll
                for (int ni = 0; ni < 4; ++ni)
                    mma_tf32(acc[mi][ni], afr[mi], bfr[ni]);
        }
        __syncthreads();
    }

    size_t obase = (size_t)b * CVCH * NPIX;
#pragma unroll
    for (int mi = 0; mi < 4; ++mi)
#pragma unroll
        for (int ni = 0; ni < 4; ++ni)
#pragma unroll
            for (int p = 0; p < 4; ++p){
                int n = n0 + warpM * 64 + mi * 16 + gid + (p >> 1) * 8;
                int c = c0 + warpN * 32 + ni * 8 + 2 * tig + (p & 1);
                outp[obase + (size_t)c * NPIX + n] = acc[mi][ni][p];
            }
}

// -------- instance-norm stats of q --------
__global__ void inorm_stats(const float* __restrict__ q, float* __restrict__ inst){
    int bc = blockIdx.x;
    const float* p = q + (size_t)bc * NPIX;
    int t = threadIdx.x;
    float s = 0.f, ss = 0.f;
    for (int i = t; i < NPIX; i += 256){ float v = p[i]; s += v; ss += v * v; }
    __shared__ float rs[256], rss[256];
    rs[t] = s; rss[t] = ss;
    __syncthreads();
    for (int o = 128; o > 0; o >>= 1){
        if (t < o){ rs[t] += rs[t + o]; rss[t] += rss[t + o]; }
        __syncthreads();
    }
    if (t == 0){
        float m = rs[0] / NPIX;
        float var = rss[0] / NPIX - m * m;
        inst[bc * 2] = m;
        inst[bc * 2 + 1] = rsqrtf(var + 1e-5f);
    }
}

// -------- fuse: ypre = out + (1-conf)*spade + q; pono stats --------
__global__ __launch_bounds__(256) void fuse1(
    const float* __restrict__ outb, const float* __restrict__ q,
    const float* __restrict__ gamma, const float* __restrict__ beta,
    const float* __restrict__ inst, const float* __restrict__ conf,
    float* __restrict__ ypre, float* __restrict__ pst)
{
    int b = blockIdx.x >> 6, y = blockIdx.x & 63;
    int tid = threadIdx.x;
    int x = tid & 63, cl = tid >> 6;
    int n = y * 64 + x;
    float one_m = 1.f - conf[(size_t)b * NPIX + n];
    size_t base = (size_t)b * CVCH * NPIX + n;
    float s = 0.f, ss = 0.f;
    for (int c = cl; c < CVCH; c += 4){
        size_t o = base + (size_t)c * NPIX;
        float qq = q[o];
        float im = inst[((size_t)b * CVCH + c) * 2];
        float is = inst[((size_t)b * CVCH + c) * 2 + 1];
        float sp = (qq - im) * is * (1.f + gamma[o]) + beta[o];
        float v = outb[o] + one_m * sp + qq;
        ypre[o] = v;
        s += v; ss += v * v;
    }
    __shared__ float rs[4][64], rss[4][64];
    rs[cl][x] = s; rss[cl][x] = ss;
    __syncthreads();
    if (cl == 0){
        float S  = rs[0][x] + rs[1][x] + rs[2][x] + rs[3][x];
        float SS = rss[0][x] + rss[1][x] + rss[2][x] + rss[3][x];
        float m = S / 256.f;
        float var = SS / 256.f - m * m;
        pst[((size_t)b * NPIX + n) * 2] = m;
        pst[((size_t)b * NPIX + n) * 2 + 1] = rsqrtf(var + 1e-5f);
    }
}

__global__ void fuse2(const float* __restrict__ ypre, const float* __restrict__ pst,
                      float* __restrict__ ypad){
    int idx = blockIdx.x * blockDim.x + threadIdx.x;
    if (idx >= BATCH * CVCH * NPIX) return;
    int n = idx & (NPIX - 1);
    int c = (idx >> 12) & 255;
    int b = idx >> 20;
    float m  = pst[((size_t)b * NPIX + n) * 2];
    float is = pst[((size_t)b * NPIX + n) * 2 + 1];
    int yy = n >> 6, xx = n & 63;
    ypad[(size_t)b * CVCH * PADN + (size_t)c * PADN + (size_t)(yy + 1) * PADW + xx + 1]
        = tf((ypre[idx] - m) * is);
}

extern "C" void kernel_launch(void* const* d_in, const int* in_sizes, int n_in,
                              void* d_out, int out_size){
    float* arena = nullptr;
    cudaGetSymbolAddress((void**)&arena, g_arena);

    const float* q    = (const float*)d_in[0];
    const float* k    = (const float*)d_in[1];
    const float* v    = (const float*)d_in[2];
    const float* pos  = (const float*)d_in[3];
    const float* v2   = (const float*)d_in[5];

    float* res  = (float*)d_out;
    float* out2 = res + (size_t)BATCH * CVCH * NPIX;
    float* cor  = out2 + (size_t)BATCH * CVCH * NPIX;

    float* QUERY = arena + OFF_QUERY;
    float* KEYT  = arena + OFF_KEYT;
    float* QF    = arena + OFF_QF;
    float* KF    = arena + OFF_KF;
    float* QP    = arena + OFF_QP;
    float* KP    = arena + OFF_KP;
    float* VH    = arena + OFF_VH;
    float* OUTB  = arena + OFF_OUT;
    float* STATS = arena + OFF_STATS;
    float* CONF  = arena + OFF_CONF;
    float* ACTV  = arena + OFF_ACTV;
    float* GAMMA = arena + OFF_GAMMA;
    float* BETA  = arena + OFF_BETA;
    float* INST  = arena + OFF_INST;
    float* YPRE  = arena + OFF_YPRE;
    float* PST   = arena + OFF_PST;
    float* YPAD  = arena + OFF_YPAD;
    float* T1PAD = arena + OFF_T1PAD;
    float* SEGP  = arena + OFF_SEGP;
    float* VHT   = arena + OFF_VHT;
    float* V2T   = arena + OFF_V2T;
    float* WT    = arena + OFF_WT;
    unsigned char* MASK = (unsigned char*)(arena + OFF_MASK);

    auto T = [&](int si, size_t off, int M, int K, int taps, int rnd){
        int tot = M * K * taps;
        transpose_w<<<(tot + 255) / 256, 256>>>((const float*)d_in[si], WT + off, M, K, taps, rnd);
    };

    long sQK = (long)CQKCH * NPIX, sCV = (long)CVCH * NPIX, sDP = (long)DPCH * NPIX;
    long sCOR = (long)NPIX * NPIX;

    T(6,  WT_F,   320, 320, 1, 1);
    T(8,  WT_G,   320, 320, 1, 1);
    pad_seg<<<(BATCH * 3 * PADN + 255) / 256, 256>>>((const float*)d_in[4], SEGP);
    norm_concat<<<dim3(BATCH * 64, 2), 256>>>(q, k, pos, QUERY, KEYT);
    T(10, WT_H,   256, 256, 1, 1);
    gemm_tf32<true><<<dim3(32, 3, 2), 256>>>(WT + WT_F,  0, 320, 320, QUERY, sQK, NPIX,
        (const float*)d_in[7],  QF, sQK, 320, 1, 0, 0, 1.f, 1, nullptr, 0);
    gemm_tf32<true><<<dim3(32, 3, 2), 256>>>(WT + WT_G,  0, 320, 320, KEYT,  sQK, NPIX,
        (const float*)d_in[9],  KF, sQK, 320, 1, 0, 0, 1.f, 1, nullptr, 0);
    gemm_tf32<true><<<dim3(32, 2, 2), 256>>>(WT + WT_H,  0, 256, 256, v,     sCV, NPIX,
        (const float*)d_in[11], VH, sCV, 256, 1, 0, 0, 1.f, 1, nullptr, 0);

    T(12, WT_FP,  64,  320, 1, 0);
    T(14, WT_GP,  64,  320, 1, 0);
    gemm_wx_f32<<<dim3(64, 1, 2), 256>>>(WT + WT_FP, QUERY, (const float*)d_in[13],
        QP, 64, 320, sQK, NPIX, sDP);
    gemm_wx_f32<<<dim3(64, 1, 2), 256>>>(WT + WT_GP, KEYT,  (const float*)d_in[15],
        KP, 64, 320, sQK, NPIX, sDP);

    T(16, WT_SPS, 128, 3,   9, 1);
    T(18, WT_SPG, 256, 128, 9, 1);
    T(20, WT_SPB, 256, 128, 9, 1);
    T(22, WT_R1,  256, 256, 9, 1);
    T(24, WT_R2,  256, 256, 9, 1);

    // cor = (QF^T KF) / sqrt(320) — both operands pre-rounded
    gemm_tf32<false><<<dim3(32, 32, 2), 256>>>(QF, sQK, NPIX, 4096, KF, sQK, NPIX,
        nullptr, cor, sCOR, 320, 1, 0, 0, 0.0559016994f, 0, nullptr, 0);
    // mask: split-tf32 on tensor pipe
    mask_split<<<dim3(32, 32, 2), 256>>>(QP, KP, MASK);

    row_stats<<<dim3(NPIX, BATCH), 256>>>(cor, MASK, STATS, CONF);

    transpose_cm<<<dim3(128, 8, 2), 256>>>(VH, VHT);
    transpose_cm<<<dim3(128, 8, 2), 256>>>(v2, V2T);

    attn_tf32<<<dim3(32, 4, 2), 256>>>(cor, MASK, STATS, VHT, V2T, OUTB, out2);

    // SPADE path
    int nACTV = BATCH * NHID * PADN, nPAD = BATCH * CVCH * PADN;
    zero_kernel<<<(nACTV + 255) / 256, 256>>>(ACTV, nACTV);
    zero_kernel<<<(nPAD + 255) / 256, 256>>>(YPAD, nPAD);
    zero_kernel<<<(nPAD + 255) / 256, 256>>>(T1PAD, nPAD);

    gemm_tf32<false><<<dim3(32, 1, 2), 256>>>(WT + WT_SPS, 0, 128, 128, SEGP, (long)3 * PADN, PADN,
        (const float*)d_in[17], ACTV, (long)NHID * PADN, 3, 9, 1, 1, 1.f, 1, nullptr, 0);
    gemm_tf32<false><<<dim3(32, 2, 2), 256>>>(WT + WT_SPG, 0, 256, 256, ACTV, (long)NHID * PADN, PADN,
        (const float*)d_in[19], GAMMA, sCV, 128, 9, 0, 0, 1.f, 0, nullptr, 0);
    gemm_tf32<false><<<dim3(32, 2, 2), 256>>>(WT + WT_SPB, 0, 256, 256, ACTV, (long)NHID * PADN, PADN,
        (const float*)d_in[21], BETA, sCV, 128, 9, 0, 0, 1.f, 0, nullptr, 0);

    inorm_stats<<<BATCH * CVCH, 256>>>(q, INST);
    fuse1<<<BATCH * 64, 256>>>(OUTB, q, GAMMA, BETA, INST, CONF, YPRE, PST);
    fuse2<<<(BATCH * CVCH * NPIX + 255) / 256, 256>>>(YPRE, PST, YPAD);

    gemm_tf32<false><<<dim3(32, 2, 2), 256>>>(WT + WT_R1, 0, 256, 256, YPAD, (long)CVCH * PADN, PADN,
        (const float*)d_in[23], T1PAD, (long)CVCH * PADN, 256, 9, 1, 1, 1.f, 1, nullptr, 0);
    gemm_tf32<false><<<dim3(32, 2, 2), 256>>>(WT + WT_R2, 0, 256, 256, T1PAD, (long)CVCH * PADN, PADN,
        (const float*)d_in[25], res, sCV, 256, 9, 0, 0, 1.f, 0, YPAD, (long)CVCH * PADN);
}

// round 14
// speedup vs baseline: 1.3309x; 1.0403x over previous
#include <cuda_runtime.h>
#include <math.h>
#include <stdint.h>

#define NPIX 4096
#define PADW 66
#define PADN 4356
#define BATCH 2
#define CVCH 256
#define CQKCH 320
#define DPCH 64
#define NHID 128

// ---------------- scratch arena ----------------
constexpr size_t SZ_QK = (size_t)BATCH * CQKCH * NPIX;
constexpr size_t SZ_CV = (size_t)BATCH * CVCH * NPIX;
constexpr size_t SZ_DP = (size_t)BATCH * DPCH * NPIX;

constexpr size_t OFF_QUERY = 0;
constexpr size_t OFF_KEYT  = OFF_QUERY + SZ_QK;
constexpr size_t OFF_QF    = OFF_KEYT + SZ_QK;
constexpr size_t OFF_KF    = OFF_QF + SZ_QK;
constexpr size_t OFF_QP    = OFF_KF + SZ_QK;
constexpr size_t OFF_KP    = OFF_QP + SZ_DP;
constexpr size_t OFF_VH    = OFF_KP + SZ_DP;
constexpr size_t OFF_OUT   = OFF_VH + SZ_CV;
constexpr size_t OFF_STATS = OFF_OUT + SZ_CV;
constexpr size_t OFF_CONF  = OFF_STATS + (size_t)BATCH*NPIX*4;
constexpr size_t OFF_ACTV  = OFF_CONF + (size_t)BATCH*NPIX;
constexpr size_t OFF_GAMMA = OFF_ACTV + (size_t)BATCH*NHID*PADN;
constexpr size_t OFF_BETA  = OFF_GAMMA + SZ_CV;
constexpr size_t OFF_INST  = OFF_BETA + SZ_CV;
constexpr size_t OFF_YPRE  = OFF_INST + (size_t)BATCH*CVCH*2;
constexpr size_t OFF_PST   = OFF_YPRE + SZ_CV;
constexpr size_t OFF_YPAD  = OFF_PST + (size_t)BATCH*NPIX*2;
constexpr size_t OFF_T1PAD = OFF_YPAD + (size_t)BATCH*CVCH*PADN;
constexpr size_t OFF_SEGP  = OFF_T1PAD + (size_t)BATCH*CVCH*PADN;
constexpr size_t OFF_VHT   = OFF_SEGP + 26176;
constexpr size_t OFF_V2T   = OFF_VHT + SZ_CV;
constexpr size_t OFF_WT    = OFF_V2T + SZ_CV;
constexpr size_t WT_F   = 0;
constexpr size_t WT_G   = WT_F  + 320*320;
constexpr size_t WT_H   = WT_G  + 320*320;
constexpr size_t WT_FP  = WT_H  + 256*256;
constexpr size_t WT_GP  = WT_FP + 320*64;
constexpr size_t WT_SPS = WT_GP + 320*64;
constexpr size_t WT_SPG = WT_SPS + 9*3*128;
constexpr size_t WT_SPB = WT_SPG + 9*128*256;
constexpr size_t WT_R1  = WT_SPB + 9*128*256;
constexpr size_t WT_R2  = WT_R1  + 9*256*256;
constexpr size_t WT_END = WT_R2  + 9*256*256;
constexpr size_t OFF_MASK = OFF_WT + ((WT_END + 63) & ~(size_t)63);
constexpr size_t ARENA_FLOATS = OFF_MASK + ((size_t)BATCH*NPIX*NPIX)/4 + 64;

__device__ __align__(16) float g_arena[ARENA_FLOATS];

// ---------------- helpers ----------------
__device__ __forceinline__ uint32_t f2tf32(float v){
    uint32_t r;
    asm("cvt.rna.tf32.f32 %0, %1;" : "=r"(r) : "f"(v));
    return r;
}
__device__ __forceinline__ float tf(float v){ return __uint_as_float(f2tf32(v)); }

__device__ __forceinline__ void mma_tf32(float* d, const uint32_t* a, const uint32_t* b){
    asm volatile("mma.sync.aligned.m16n8k8.row.col.f32.tf32.tf32.f32 "
        "{%0,%1,%2,%3}, {%4,%5,%6,%7}, {%8,%9}, {%0,%1,%2,%3};"
        : "+f"(d[0]), "+f"(d[1]), "+f"(d[2]), "+f"(d[3])
        : "r"(a[0]), "r"(a[1]), "r"(a[2]), "r"(a[3]), "r"(b[0]), "r"(b[1]));
}

__device__ __forceinline__ void cp16(void* smem, const void* gmem, int sz){
    uint32_t sa = (uint32_t)__cvta_generic_to_shared(smem);
    asm volatile("cp.async.cg.shared.global [%0], [%1], 16, %2;"
                 :: "r"(sa), "l"(gmem), "r"(sz));
}
__device__ __forceinline__ void cp4(void* smem, const void* gmem, int sz){
    uint32_t sa = (uint32_t)__cvta_generic_to_shared(smem);
    asm volatile("cp.async.ca.shared.global [%0], [%1], 4, %2;"
                 :: "r"(sa), "l"(gmem), "r"(sz));
}
__device__ __forceinline__ void cp_commit(){ asm volatile("cp.async.commit_group;"); }
__device__ __forceinline__ void cp_wait1(){ asm volatile("cp.async.wait_group 1;"); }

__device__ __forceinline__ float fast_exp(float x){
    float t = x * 1.4426950408889634f;
    t = fmaxf(t, -126.0f);
    float tr = t + 12582912.0f;
    int   k  = __float_as_int(tr) - 0x4B400000;
    float fi = tr - 12582912.0f;
    float f  = t - fi;
    float p = 1.0f + f*(0.6931471805599453f + f*(0.2402265069591007f
              + f*(0.0555041086648216f + f*0.0096181291076285f)));
    return p * __int_as_float((k + 127) << 23);
}

// ---------------- utility kernels ----------------
__global__ void zero_kernel(float* p, int n){
    int i = blockIdx.x * blockDim.x + threadIdx.x;
    if (i < n) p[i] = 0.f;
}

__global__ void transpose_w(const float* __restrict__ src, float* __restrict__ dst,
                            int M, int K, int taps, int rnd){
    int idx = blockIdx.x * blockDim.x + threadIdx.x;
    if (idx >= M * K * taps) return;
    int t = idx / (K * M);
    int r = idx % (K * M);
    int k = r / M;
    int m = r % M;
    float v = src[((size_t)m * K + k) * taps + t];
    dst[idx] = rnd ? tf(v) : v;
}

// [b][c][m] -> [b][m][c], tf32-rounded
__global__ __launch_bounds__(256) void transpose_cm(const float* __restrict__ src,
                                                    float* __restrict__ dst){
    __shared__ float s[32][33];
    int mBase = blockIdx.x * 32, cBase = blockIdx.y * 32, b = blockIdx.z;
    int tx = threadIdx.x & 31, ty = threadIdx.x >> 5;
    size_t base = (size_t)b * CVCH * NPIX;
#pragma unroll
    for (int i = 0; i < 4; ++i){
        int c = cBase + ty + i * 8;
        s[ty + i * 8][tx] = src[base + (size_t)c * NPIX + mBase + tx];
    }
    __syncthreads();
#pragma unroll
    for (int i = 0; i < 4; ++i){
        int m = mBase + ty + i * 8;
        dst[base + (size_t)m * CVCH + cBase + tx] = tf(s[tx][ty + i * 8]);
    }
}

__global__ void pad_seg(const float* __restrict__ seg, float* __restrict__ dst){
    int idx = blockIdx.x * blockDim.x + threadIdx.x;
    if (idx >= BATCH * 3 * PADN) return;
    int bc = idx / PADN;
    int r = idx % PADN;
    int yy = r / PADW, xx = r % PADW;
    float v = 0.f;
    if (yy >= 1 && yy <= 64 && xx >= 1 && xx <= 64)
        v = seg[(size_t)bc * NPIX + (yy - 1) * 64 + (xx - 1)];
    dst[idx] = tf(v);
}

__global__ __launch_bounds__(256) void norm_concat(
    const float* __restrict__ q, const float* __restrict__ k,
    const float* __restrict__ pos, float* __restrict__ outq, float* __restrict__ outk){
    const float* src = blockIdx.y ? k : q;
    float* dst = blockIdx.y ? outk : outq;
    int b = blockIdx.x / 64, y = blockIdx.x % 64;
    int tid = threadIdx.x;
    int x = tid & 63, cl = tid >> 6;
    const float* sb = src + (size_t)b * CVCH * NPIX + y * 64;
    __shared__ float partial[4][64];
    __shared__ float inv[64];
    float ss = 0.f;
    for (int c = cl; c < CVCH; c += 4){ float v = sb[(size_t)c * NPIX + x]; ss += v * v; }
    partial[cl][x] = ss;
    __syncthreads();
    if (cl == 0){
        float s = partial[0][x] + partial[1][x] + partial[2][x] + partial[3][x];
        inv[x] = 1.f / (sqrtf(s) + 2.220446049250313e-16f);
    }
    __syncthreads();
    float* db = dst + (size_t)b * CQKCH * NPIX + y * 64;
    float iv = inv[x];
    for (int c = cl; c < CVCH; c += 4) db[(size_t)c * NPIX + x] = sb[(size_t)c * NPIX + x] * iv;
    const float* pb = pos + y * 64;
    for (int i = tid; i < 64 * 64; i += 256){
        int cp = i >> 6, xx = i & 63;
        db[(size_t)(CVCH + cp) * NPIX + xx] = pb[(size_t)cp * NPIX + xx];
    }
}

// ------------- exact-fp32 1x1 conv GEMM (QP/KP — mask sign sensitivity) -------------
__global__ __launch_bounds__(256) void gemm_wx_f32(
    const float* __restrict__ Wt, const float* __restrict__ X,
    const float* __restrict__ bias, float* __restrict__ Cout,
    int M, int K, long xBatchStride, int xChanStride, long cBatchStride)
{
    int b = blockIdx.z;
    int n0 = blockIdx.x * 64;
    int m0 = blockIdx.y * 64;
    const float* Xb = X + (size_t)b * xBatchStride;
    __shared__ __align__(16) float As[16][64];
    __shared__ __align__(16) float Bs[16][64];
    float acc[4][4] = {};
    int tid = threadIdx.x;
    int tx = tid & 15, ty = tid >> 4;
    for (int k0 = 0; k0 < K; k0 += 16){
#pragma unroll
        for (int i = 0; i < 4; ++i){
            int idx = tid + 256 * i;
            int kk = idx >> 6, col = idx & 63;
            int kg = k0 + kk;
            As[kk][col] = (kg < K) ? Wt[(size_t)kg * M + m0 + col] : 0.f;
            Bs[kk][col] = (kg < K) ? Xb[(size_t)kg * xChanStride + n0 + col] : 0.f;
        }
        __syncthreads();
#pragma unroll
        for (int kk = 0; kk < 16; ++kk){
            float4 a  = *(const float4*)&As[kk][ty * 4];
            float4 bb = *(const float4*)&Bs[kk][tx * 4];
            float av[4] = {a.x, a.y, a.z, a.w};
            float bv[4] = {bb.x, bb.y, bb.z, bb.w};
#pragma unroll
            for (int i = 0; i < 4; ++i)
#pragma unroll
                for (int j = 0; j < 4; ++j)
                    acc[i][j] += av[i] * bv[j];
        }
        __syncthreads();
    }
#pragma unroll
    for (int i = 0; i < 4; ++i){
        int m = m0 + ty * 4 + i;
        float bvv = bias ? bias[m] : 0.f;
#pragma unroll
        for (int j = 0; j < 4; ++j)
            Cout[(size_t)b * cBatchStride + (size_t)m * NPIX + n0 + tx * 4 + j] = acc[i][j] + bvv;
    }
}

// ------------- tf32 tensor GEMM: block 128Mx128N, warp 64x32, 2 CTAs/SM -------------
// CVTB=true: synchronous loads with in-flight tf32 convert (raw fp32 B inputs).
// CVTB=false: 2-stage cp.async pipeline (all operands pre-rounded).
template<bool CVTB>
__global__ __launch_bounds__(256, 2) void gemm_tf32(
    const float* __restrict__ A, long aBatchStride, int aRowStride, int M,
    const float* __restrict__ X, long xBatchStride, int xChanStride,
    const float* __restrict__ bias, float* __restrict__ Cout, long cBatchStride,
    int K, int taps, int relu, int outPadded, float scale, int roundOut,
    const float* __restrict__ addsrc, long addBatchStride)
{
    int b = blockIdx.z;
    int n0 = blockIdx.x * 128;
    int m0 = blockIdx.y * 128;
    const float* A_ = A + (size_t)b * aBatchStride;
    const float* Xb = X + (size_t)b * xBatchStride;
    __shared__ float As[2][16][136];
    __shared__ float Bs[2][16][136];
    int tid = threadIdx.x;
    int wid = tid >> 5, lane = tid & 31;
    int gid = lane >> 2, tig = lane & 3;
    int warpM = wid & 1, warpN = wid >> 1;
    float acc[4][4][4];
#pragma unroll
    for (int mi = 0; mi < 4; ++mi)
#pragma unroll
        for (int ni = 0; ni < 4; ++ni)
#pragma unroll
            for (int p = 0; p < 4; ++p) acc[mi][ni][p] = 0.f;

    int Ktot = K * taps;
    int nIter = (Ktot + 15) >> 4;

    auto do_mma = [&](int st){
#pragma unroll
        for (int ks = 0; ks < 16; ks += 8){
            uint32_t afr[4][4], bfr[4][2];
#pragma unroll
            for (int mi = 0; mi < 4; ++mi){
                int mb = warpM * 64 + mi * 16 + gid;
                afr[mi][0] = __float_as_uint(As[st][ks + tig][mb]);
                afr[mi][1] = __float_as_uint(As[st][ks + tig][mb + 8]);
                afr[mi][2] = __float_as_uint(As[st][ks + tig + 4][mb]);
                afr[mi][3] = __float_as_uint(As[st][ks + tig + 4][mb + 8]);
            }
#pragma unroll
            for (int ni = 0; ni < 4; ++ni){
                int nb = warpN * 32 + ni * 8 + gid;
                bfr[ni][0] = __float_as_uint(Bs[st][ks + tig][nb]);
                bfr[ni][1] = __float_as_uint(Bs[st][ks + tig + 4][nb]);
            }
#pragma unroll
            for (int mi = 0; mi < 4; ++mi)
#pragma unroll
                for (int ni = 0; ni < 4; ++ni)
                    mma_tf32(acc[mi][ni], afr[mi], bfr[ni]);
        }
    };

    if (CVTB){
        // synchronous path (small GEMMs with raw-fp32 B)
        for (int it = 0; it < nIter; ++it){
            int k0 = it * 16;
#pragma unroll
            for (int i = 0; i < 2; ++i){
                int qi = tid + i * 256;
                int kk = qi >> 5, m = (qi & 31) * 4;
                int kg = k0 + kk;
                float4 v = make_float4(0.f, 0.f, 0.f, 0.f);
                if (kg < Ktot && m0 + m < M)
                    v = *(const float4*)&A_[(size_t)kg * aRowStride + m0 + m];
                As[0][kk][m]     = v.x;
                As[0][kk][m + 1] = v.y;
                As[0][kk][m + 2] = v.z;
                As[0][kk][m + 3] = v.w;
            }
#pragma unroll
            for (int i = 0; i < 2; ++i){
                int qi = tid + i * 256;
                int kk = qi >> 5, col = (qi & 31) * 4;
                int kg = k0 + kk;
                float4 v = make_float4(0.f, 0.f, 0.f, 0.f);
                if (kg < Ktot)
                    v = *(const float4*)&Xb[(size_t)kg * xChanStride + n0 + col];
                Bs[0][kk][col]     = tf(v.x);
                Bs[0][kk][col + 1] = tf(v.y);
                Bs[0][kk][col + 2] = tf(v.z);
                Bs[0][kk][col + 3] = tf(v.w);
            }
            __syncthreads();
            do_mma(0);
            __syncthreads();
        }
    } else {
        // cp.async 2-stage pipeline
        auto load_tiles = [&](int it, int st){
            int k0 = it * 16;
#pragma unroll
            for (int i = 0; i < 2; ++i){
                int qi = tid + i * 256;
                int kk = qi >> 5, m = (qi & 31) * 4;
                int kg = k0 + kk;
                int ok = (kg < Ktot) && (m0 + m < M);
                const float* g = ok ? &A_[(size_t)kg * aRowStride + m0 + m] : A_;
                cp16(&As[st][kk][m], g, ok ? 16 : 0);
            }
            if (taps == 1){
#pragma unroll
                for (int i = 0; i < 2; ++i){
                    int qi = tid + i * 256;
                    int kk = qi >> 5, col = (qi & 31) * 4;
                    int kg = k0 + kk;
                    int ok = (kg < Ktot);
                    const float* g = ok ? &Xb[(size_t)kg * xChanStride + n0 + col] : Xb;
                    cp16(&Bs[st][kk][col], g, ok ? 16 : 0);
                }
            } else {
#pragma unroll
                for (int i = 0; i < 8; ++i){
                    int idx = tid + i * 256;
                    int kk = idx >> 7, col = idx & 127;
                    int kg = k0 + kk;
                    const float* g = Xb;
                    int ok = (kg < Ktot);
                    if (ok){
                        int tap = kg / K, kr = kg - tap * K, ky = tap / 3, kx = tap % 3;
                        int n = n0 + col, yy = n >> 6, xx = n & 63;
                        g = &Xb[(size_t)kr * xChanStride + (yy + ky) * PADW + xx + kx];
                    }
                    cp4(&Bs[st][kk][col], g, ok ? 4 : 0);
                }
            }
        };
        load_tiles(0, 0);
        cp_commit();
        for (int it = 0; it < nIter; ++it){
            int st = it & 1;
            if (it + 1 < nIter) load_tiles(it + 1, st ^ 1);
            cp_commit();
            cp_wait1();
            __syncthreads();
            do_mma(st);
            __syncthreads();
        }
    }

    size_t cb = (size_t)b * cBatchStride;
#pragma unroll
    for (int mi = 0; mi < 4; ++mi)
#pragma unroll
        for (int ni = 0; ni < 4; ++ni)
#pragma unroll
            for (int p = 0; p < 4; ++p){
                int row = m0 + warpM * 64 + mi * 16 + gid + (p >> 1) * 8;
                if (row >= M) continue;
                int n   = n0 + warpN * 32 + ni * 8 + 2 * tig + (p & 1);
                float vv = acc[mi][ni][p] * scale + (bias ? bias[row] : 0.f);
                if (relu) vv = fmaxf(vv, 0.f);
                if (roundOut) vv = tf(vv);
                int yy = n >> 6, xx = n & 63;
                if (addsrc)
                    vv += addsrc[(size_t)b * addBatchStride + (size_t)row * PADN + (size_t)(yy + 1) * PADW + xx + 1];
                if (outPadded)
                    Cout[cb + (size_t)row * PADN + (size_t)(yy + 1) * PADW + xx + 1] = vv;
                else
                    Cout[cb + (size_t)row * NPIX + n] = vv;
            }
}

// ---------------- mask GEMM: split-tf32, block 128x128, warp 64x32 ----------------
__global__ __launch_bounds__(256, 2) void mask_split(
    const float* __restrict__ qp, const float* __restrict__ kp,
    unsigned char* __restrict__ mask)
{
    int b = blockIdx.z;
    int n0 = blockIdx.y * 128, m0 = blockIdx.x * 128;
    const float* Ap = qp + (size_t)b * DPCH * NPIX;
    const float* Bp = kp + (size_t)b * DPCH * NPIX;
    __shared__ float As[16][136];
    __shared__ float Bs[16][136];
    int tid = threadIdx.x;
    int wid = tid >> 5, lane = tid & 31;
    int gid = lane >> 2, tig = lane & 3;
    int warpM = wid & 1, warpN = wid >> 1;
    float acc[4][4][4];
#pragma unroll
    for (int mi = 0; mi < 4; ++mi)
#pragma unroll
        for (int ni = 0; ni < 4; ++ni)
#pragma unroll
            for (int p = 0; p < 4; ++p) acc[mi][ni][p] = 0.f;

    for (int k0 = 0; k0 < 192; k0 += 16){
        int seg = k0 >> 6;
        int krb = k0 & 63;
#pragma unroll
        for (int i = 0; i < 2; ++i){
            int qi = tid + i * 256;
            int kk = qi >> 5, m = (qi & 31) * 4;
            float4 v = *(const float4*)&Ap[(size_t)(krb + kk) * NPIX + n0 + m];
            float sv[4] = {v.x, v.y, v.z, v.w};
#pragma unroll
            for (int j = 0; j < 4; ++j){
                uint32_t hi = f2tf32(sv[j]);
                uint32_t o = hi;
                if (seg == 1){ float lo = sv[j] - __uint_as_float(hi); o = f2tf32(lo); }
                As[kk][m + j] = __uint_as_float(o);
            }
        }
#pragma unroll
        for (int i = 0; i < 2; ++i){
            int qi = tid + i * 256;
            int kk = qi >> 5, col = (qi & 31) * 4;
            float4 v = *(const float4*)&Bp[(size_t)(krb + kk) * NPIX + m0 + col];
            float sv[4] = {v.x, v.y, v.z, v.w};
#pragma unroll
            for (int j = 0; j < 4; ++j){
                uint32_t hi = f2tf32(sv[j]);
                uint32_t o = hi;
                if (seg == 2){ float lo = sv[j] - __uint_as_float(hi); o = f2tf32(lo); }
                Bs[kk][col + j] = __uint_as_float(o);
            }
        }
        __syncthreads();
#pragma unroll
        for (int ks = 0; ks < 16; ks += 8){
            uint32_t afr[4][4], bfr[4][2];
#pragma unroll
            for (int mi = 0; mi < 4; ++mi){
                int mb = warpM * 64 + mi * 16 + gid;
                afr[mi][0] = __float_as_uint(As[ks + tig][mb]);
                afr[mi][1] = __float_as_uint(As[ks + tig][mb + 8]);
                afr[mi][2] = __float_as_uint(As[ks + tig + 4][mb]);
                afr[mi][3] = __float_as_uint(As[ks + tig + 4][mb + 8]);
            }
#pragma unroll
            for (int ni = 0; ni < 4; ++ni){
                int nb = warpN * 32 + ni * 8 + gid;
                bfr[ni][0] = __float_as_uint(Bs[ks + tig][nb]);
                bfr[ni][1] = __float_as_uint(Bs[ks + tig + 4][nb]);
            }
#pragma unroll
            for (int mi = 0; mi < 4; ++mi)
#pragma unroll
                for (int ni = 0; ni < 4; ++ni)
                    mma_tf32(acc[mi][ni], afr[mi], bfr[ni]);
        }
        __syncthreads();
    }
    size_t base = (size_t)b * NPIX * NPIX;
#pragma unroll
    for (int mi = 0; mi < 4; ++mi)
#pragma unroll
        for (int ni = 0; ni < 4; ++ni)
#pragma unroll
            for (int p = 0; p < 4; ++p){
                int n = n0 + warpM * 64 + mi * 16 + gid + (p >> 1) * 8;
                int m = m0 + warpN * 32 + ni * 8 + 2 * tig + (p & 1);
                mask[base + (size_t)n * NPIX + m] = (acc[mi][ni][p] > 0.f) ? 1 : 0;
            }
}

// -------- per-row softmax stats (both variants) + conf, vectorized --------
__global__ __launch_bounds__(256) void row_stats(
    const float* __restrict__ cor, const unsigned char* __restrict__ mask,
    float* __restrict__ stats, float* __restrict__ conf)
{
    int b = blockIdx.y, n = blockIdx.x;
    const float* row = cor + ((size_t)b * NPIX + n) * NPIX;
    const unsigned char* mrow = mask + ((size_t)b * NPIX + n) * NPIX;
    int t = threadIdx.x;
    float m1 = -1e30f, m2 = -1e30f;
    for (int i = t * 4; i < NPIX; i += 1024){
        float4 s4 = *(const float4*)&row[i];
        unsigned int mk4 = *(const unsigned int*)&mrow[i];
        float sv[4] = {s4.x, s4.y, s4.z, s4.w};
#pragma unroll
        for (int j = 0; j < 4; ++j){
            m1 = fmaxf(m1, sv[j]);
            m2 = fmaxf(m2, ((mk4 >> (8 * j)) & 0xff) ? -10000.f : sv[j]);
        }
    }
    __shared__ float r1[256], r2[256], r3[256];
    r1[t] = m1; r2[t] = m2;
    __syncthreads();
    for (int o = 128; o > 0; o >>= 1){
        if (t < o){ r1[t] = fmaxf(r1[t], r1[t + o]); r2[t] = fmaxf(r2[t], r2[t + o]); }
        __syncthreads();
    }
    float M1 = r1[0], M2 = r2[0];
    __syncthreads();
    float d1 = 0.f, num = 0.f, d2 = 0.f;
    for (int i = t * 4; i < NPIX; i += 1024){
        float4 s4 = *(const float4*)&row[i];
        unsigned int mk4 = *(const unsigned int*)&mrow[i];
        float sv[4] = {s4.x, s4.y, s4.z, s4.w};
#pragma unroll
        for (int j = 0; j < 4; ++j){
            int mk = (mk4 >> (8 * j)) & 0xff;
            float e1 = fast_exp(sv[j] - M1);
            d1 += e1;
            num += mk ? e1 : 0.f;
            d2 += fast_exp((mk ? -10000.f : sv[j]) - M2);
        }
    }
    r1[t] = d1; r2[t] = num; r3[t] = d2;
    __syncthreads();
    for (int o = 128; o > 0; o >>= 1){
        if (t < o){ r1[t] += r1[t + o]; r2[t] += r2[t + o]; r3[t] += r3[t + o]; }
        __syncthreads();
    }
    if (t == 0){
        float* st = stats + ((size_t)b * NPIX + n) * 4;
        st[0] = M1; st[1] = r1[0]; st[2] = M2; st[3] = r3[0];
        conf[(size_t)b * NPIX + n] = r2[0] / r1[0];
    }
}

// -------- tensor attention: block 128n x 128c, warp 64x32, pipelined --------
// grid: (32, 4, BATCH); var = y>>1, c0 = (y&1)*128
__global__ __launch_bounds__(256, 2) void attn_tf32(
    const float* __restrict__ cor, const unsigned char* __restrict__ mask,
    const float* __restrict__ stats, const float* __restrict__ VT1,
    const float* __restrict__ VT2, float* __restrict__ out1, float* __restrict__ out2)
{
    int b = blockIdx.z;
    int var = blockIdx.y >> 1;
    int c0 = (blockIdx.y & 1) * 128;
    int n0 = blockIdx.x * 128;
    const float* VT = var ? VT2 : VT1;
    float* outp = var ? out2 : out1;
    __shared__ float Ps[16][136];
    __shared__ float Vs[2][16][136];
    int tid = threadIdx.x;
    int wid = tid >> 5, lane = tid & 31;
    int gid = lane >> 2, tig = lane & 3;
    int warpM = wid & 1, warpN = wid >> 1;

    int pr = tid & 127, half = tid >> 7;
    const float* st_ = stats + ((size_t)b * NPIX + n0 + pr) * 4;
    float Mv = var ? st_[2] : st_[0];
    float Dv = 1.f / (var ? st_[3] : st_[1]);

    const float* corb = cor + (size_t)b * NPIX * NPIX;
    const unsigned char* mb = mask + (size_t)b * NPIX * NPIX;
    const float* VTb = VT + (size_t)b * NPIX * CVCH;

    float acc[4][4][4];
#pragma unroll
    for (int mi = 0; mi < 4; ++mi)
#pragma unroll
        for (int ni = 0; ni < 4; ++ni)
#pragma unroll
            for (int p = 0; p < 4; ++p) acc[mi][ni][p] = 0.f;

    auto loadV = [&](int it, int st){
#pragma unroll
        for (int i = 0; i < 2; ++i){
            int qi = tid + i * 256;
            int kk = qi >> 5, c = (qi & 31) * 4;
            cp16(&Vs[st][kk][c], &VTb[(size_t)(it * 16 + kk) * CVCH + c0 + c], 16);
        }
    };

    // prologue: prefetch cor regs for it=0, V async for it=0
    float4 pc0, pc1; uint2 pmk;
    {
        size_t off = (size_t)(n0 + pr) * NPIX + half * 8;
        pc0 = *(const float4*)&corb[off];
        pc1 = *(const float4*)&corb[off + 4];
        pmk = *(const uint2*)&mb[off];
    }
    loadV(0, 0);
    cp_commit();

    const int nIter = NPIX / 16;
    for (int it = 0; it < nIter; ++it){
        int st = it & 1;
        float4 nc0 = make_float4(0,0,0,0), nc1 = make_float4(0,0,0,0);
        uint2 nmk = make_uint2(0,0);
        if (it + 1 < nIter){
            size_t off = (size_t)(n0 + pr) * NPIX + (it + 1) * 16 + half * 8;
            nc0 = *(const float4*)&corb[off];
            nc1 = *(const float4*)&corb[off + 4];
            nmk = *(const uint2*)&mb[off];
            loadV(it + 1, st ^ 1);
        }
        cp_commit();
        // build P(it) from prefetched regs
        {
            float sv[8] = {pc0.x, pc0.y, pc0.z, pc0.w, pc1.x, pc1.y, pc1.z, pc1.w};
#pragma unroll
            for (int j = 0; j < 8; ++j){
                int mk = (j < 4 ? (pmk.x >> (8 * j)) : (pmk.y >> (8 * (j - 4)))) & 0xff;
                float p;
                if (var == 0) p = mk ? __expf(sv[j] - Mv) * Dv : 0.f;
                else          p = __expf((mk ? -10000.f : sv[j]) - Mv) * Dv;
                Ps[half * 8 + j][pr] = tf(p);
            }
        }
        cp_wait1();
        __syncthreads();
#pragma unroll
        for (int ks = 0; ks < 16; ks += 8){
            uint32_t afr[4][4], bfr[4][2];
#pragma unroll
            for (int mi = 0; mi < 4; ++mi){
                int mbx = warpM * 64 + mi * 16 + gid;
                afr[mi][0] = __float_as_uint(Ps[ks + tig][mbx]);
                afr[mi][1] = __float_as_uint(Ps[ks + tig][mbx + 8]);
                afr[mi][2] = __float_as_uint(Ps[ks + tig + 4][mbx]);
                afr[mi][3] = __float_as_uint(Ps[ks + tig + 4][mbx + 8]);
            }
#pragma unroll
            for (int ni = 0; ni < 4; ++ni){
                int nb = warpN * 32 + ni * 8 + gid;
                bfr[ni][0] = __float_as_uint(Vs[st][ks + tig][nb]);
                bfr[ni][1] = __float_as_uint(Vs[st][ks + tig + 4][nb]);
            }
#pragma unroll
            for (int mi = 0; mi < 4; ++mi)
#pragma unroll
                for (int ni = 0; ni < 4; ++ni)
                    mma_tf32(acc[mi][ni], afr[mi], bfr[ni]);
        }
        __syncthreads();
        pc0 = nc0; pc1 = nc1; pmk = nmk;
    }

    size_t obase = (size_t)b * CVCH * NPIX;
#pragma unroll
    for (int mi = 0; mi < 4; ++mi)
#pragma unroll
        for (int ni = 0; ni < 4; ++ni)
#pragma unroll
            for (int p = 0; p < 4; ++p){
                int n = n0 + warpM * 64 + mi * 16 + gid + (p >> 1) * 8;
                int c = c0 + warpN * 32 + ni * 8 + 2 * tig + (p & 1);
                outp[obase + (size_t)c * NPIX + n] = acc[mi][ni][p];
            }
}

// -------- instance-norm stats of q --------
__global__ void inorm_stats(const float* __restrict__ q, float* __restrict__ inst){
    int bc = blockIdx.x;
    const float* p = q + (size_t)bc * NPIX;
    int t = threadIdx.x;
    float s = 0.f, ss = 0.f;
    for (int i = t; i < NPIX; i += 256){ float v = p[i]; s += v; ss += v * v; }
    __shared__ float rs[256], rss[256];
    rs[t] = s; rss[t] = ss;
    __syncthreads();
    for (int o = 128; o > 0; o >>= 1){
        if (t < o){ rs[t] += rs[t + o]; rss[t] += rss[t + o]; }
        __syncthreads();
    }
    if (t == 0){
        float m = rs[0] / NPIX;
        float var = rss[0] / NPIX - m * m;
        inst[bc * 2] = m;
        inst[bc * 2 + 1] = rsqrtf(var + 1e-5f);
    }
}

// -------- fuse: ypre = out + (1-conf)*spade + q; pono stats --------
__global__ __launch_bounds__(256) void fuse1(
    const float* __restrict__ outb, const float* __restrict__ q,
    const float* __restrict__ gamma, const float* __restrict__ beta,
    const float* __restrict__ inst, const float* __restrict__ conf,
    float* __restrict__ ypre, float* __restrict__ pst)
{
    int b = blockIdx.x >> 6, y = blockIdx.x & 63;
    int tid = threadIdx.x;
    int x = tid & 63, cl = tid >> 6;
    int n = y * 64 + x;
    float one_m = 1.f - conf[(size_t)b * NPIX + n];
    size_t base = (size_t)b * CVCH * NPIX + n;
    float s = 0.f, ss = 0.f;
    for (int c = cl; c < CVCH; c += 4){
        size_t o = base + (size_t)c * NPIX;
        float qq = q[o];
        float im = inst[((size_t)b * CVCH + c) * 2];
        float is = inst[((size_t)b * CVCH + c) * 2 + 1];
        float sp = (qq - im) * is * (1.f + gamma[o]) + beta[o];
        float v = outb[o] + one_m * sp + qq;
        ypre[o] = v;
        s += v; ss += v * v;
    }
    __shared__ float rs[4][64], rss[4][64];
    rs[cl][x] = s; rss[cl][x] = ss;
    __syncthreads();
    if (cl == 0){
        float S  = rs[0][x] + rs[1][x] + rs[2][x] + rs[3][x];
        float SS = rss[0][x] + rss[1][x] + rss[2][x] + rss[3][x];
        float m = S / 256.f;
        float var = SS / 256.f - m * m;
        pst[((size_t)b * NPIX + n) * 2] = m;
        pst[((size_t)b * NPIX + n) * 2 + 1] = rsqrtf(var + 1e-5f);
    }
}

__global__ void fuse2(const float* __restrict__ ypre, const float* __restrict__ pst,
                      float* __restrict__ ypad){
    int idx = blockIdx.x * blockDim.x + threadIdx.x;
    if (idx >= BATCH * CVCH * NPIX) return;
    int n = idx & (NPIX - 1);
    int c = (idx >> 12) & 255;
    int b = idx >> 20;
    float m  = pst[((size_t)b * NPIX + n) * 2];
    float is = pst[((size_t)b * NPIX + n) * 2 + 1];
    int yy = n >> 6, xx = n & 63;
    ypad[(size_t)b * CVCH * PADN + (size_t)c * PADN + (size_t)(yy + 1) * PADW + xx + 1]
        = tf((ypre[idx] - m) * is);
}

extern "C" void kernel_launch(void* const* d_in, const int* in_sizes, int n_in,
                              void* d_out, int out_size){
    float* arena = nullptr;
    cudaGetSymbolAddress((void**)&arena, g_arena);

    const float* q    = (const float*)d_in[0];
    const float* k    = (const float*)d_in[1];
    const float* v    = (const float*)d_in[2];
    const float* pos  = (const float*)d_in[3];
    const float* v2   = (const float*)d_in[5];

    float* res  = (float*)d_out;
    float* out2 = res + (size_t)BATCH * CVCH * NPIX;
    float* cor  = out2 + (size_t)BATCH * CVCH * NPIX;

    float* QUERY = arena + OFF_QUERY;
    float* KEYT  = arena + OFF_KEYT;
    float* QF    = arena + OFF_QF;
    float* KF    = arena + OFF_KF;
    float* QP    = arena + OFF_QP;
    float* KP    = arena + OFF_KP;
    float* VH    = arena + OFF_VH;
    float* OUTB  = arena + OFF_OUT;
    float* STATS = arena + OFF_STATS;
    float* CONF  = arena + OFF_CONF;
    float* ACTV  = arena + OFF_ACTV;
    float* GAMMA = arena + OFF_GAMMA;
    float* BETA  = arena + OFF_BETA;
    float* INST  = arena + OFF_INST;
    float* YPRE  = arena + OFF_YPRE;
    float* PST   = arena + OFF_PST;
    float* YPAD  = arena + OFF_YPAD;
    float* T1PAD = arena + OFF_T1PAD;
    float* SEGP  = arena + OFF_SEGP;
    float* VHT   = arena + OFF_VHT;
    float* V2T   = arena + OFF_V2T;
    float* WT    = arena + OFF_WT;
    unsigned char* MASK = (unsigned char*)(arena + OFF_MASK);

    auto T = [&](int si, size_t off, int M, int K, int taps, int rnd){
        int tot = M * K * taps;
        transpose_w<<<(tot + 255) / 256, 256>>>((const float*)d_in[si], WT + off, M, K, taps, rnd);
    };

    long sQK = (long)CQKCH * NPIX, sCV = (long)CVCH * NPIX, sDP = (long)DPCH * NPIX;
    long sCOR = (long)NPIX * NPIX;

    T(6,  WT_F,   320, 320, 1, 1);
    T(8,  WT_G,   320, 320, 1, 1);
    pad_seg<<<(BATCH * 3 * PADN + 255) / 256, 256>>>((const float*)d_in[4], SEGP);
    norm_concat<<<dim3(BATCH * 64, 2), 256>>>(q, k, pos, QUERY, KEYT);
    T(10, WT_H,   256, 256, 1, 1);
    gemm_tf32<true><<<dim3(32, 3, 2), 256>>>(WT + WT_F,  0, 320, 320, QUERY, sQK, NPIX,
        (const float*)d_in[7],  QF, sQK, 320, 1, 0, 0, 1.f, 1, nullptr, 0);
    gemm_tf32<true><<<dim3(32, 3, 2), 256>>>(WT + WT_G,  0, 320, 320, KEYT,  sQK, NPIX,
        (const float*)d_in[9],  KF, sQK, 320, 1, 0, 0, 1.f, 1, nullptr, 0);
    gemm_tf32<true><<<dim3(32, 2, 2), 256>>>(WT + WT_H,  0, 256, 256, v,     sCV, NPIX,
        (const float*)d_in[11], VH, sCV, 256, 1, 0, 0, 1.f, 1, nullptr, 0);

    T(12, WT_FP,  64,  320, 1, 0);
    T(14, WT_GP,  64,  320, 1, 0);
    gemm_wx_f32<<<dim3(64, 1, 2), 256>>>(WT + WT_FP, QUERY, (const float*)d_in[13],
        QP, 64, 320, sQK, NPIX, sDP);
    gemm_wx_f32<<<dim3(64, 1, 2), 256>>>(WT + WT_GP, KEYT,  (const float*)d_in[15],
        KP, 64, 320, sQK, NPIX, sDP);

    T(16, WT_SPS, 128, 3,   9, 1);
    T(18, WT_SPG, 256, 128, 9, 1);
    T(20, WT_SPB, 256, 128, 9, 1);
    T(22, WT_R1,  256, 256, 9, 1);
    T(24, WT_R2,  256, 256, 9, 1);

    // cor = (QF^T KF) / sqrt(320) — pipelined, pre-rounded operands
    gemm_tf32<false><<<dim3(32, 32, 2), 256>>>(QF, sQK, NPIX, 4096, KF, sQK, NPIX,
        nullptr, cor, sCOR, 320, 1, 0, 0, 0.0559016994f, 0, nullptr, 0);
    mask_split<<<dim3(32, 32, 2), 256>>>(QP, KP, MASK);

    row_stats<<<dim3(NPIX, BATCH), 256>>>(cor, MASK, STATS, CONF);

    transpose_cm<<<dim3(128, 8, 2), 256>>>(VH, VHT);
    transpose_cm<<<dim3(128, 8, 2), 256>>>(v2, V2T);

    attn_tf32<<<dim3(32, 4, 2), 256>>>(cor, MASK, STATS, VHT, V2T, OUTB, out2);

    // SPADE path
    int nACTV = BATCH * NHID * PADN, nPAD = BATCH * CVCH * PADN;
    zero_kernel<<<(nACTV + 255) / 256, 256>>>(ACTV, nACTV);
    zero_kernel<<<(nPAD + 255) / 256, 256>>>(YPAD, nPAD);
    zero_kernel<<<(nPAD + 255) / 256, 256>>>(T1PAD, nPAD);

    gemm_tf32<false><<<dim3(32, 1, 2), 256>>>(WT + WT_SPS, 0, 128, 128, SEGP, (long)3 * PADN, PADN,
        (const float*)d_in[17], ACTV, (long)NHID * PADN, 3, 9, 1, 1, 1.f, 1, nullptr, 0);
    gemm_tf32<false><<<dim3(32, 2, 2), 256>>>(WT + WT_SPG, 0, 256, 256, ACTV, (long)NHID * PADN, PADN,
        (const float*)d_in[19], GAMMA, sCV, 128, 9, 0, 0, 1.f, 0, nullptr, 0);
    gemm_tf32<false><<<dim3(32, 2, 2), 256>>>(WT + WT_SPB, 0, 256, 256, ACTV, (long)NHID * PADN, PADN,
        (const float*)d_in[21], BETA, sCV, 128, 9, 0, 0, 1.f, 0, nullptr, 0);

    inorm_stats<<<BATCH * CVCH, 256>>>(q, INST);
    fuse1<<<BATCH * 64, 256>>>(OUTB, q, GAMMA, BETA, INST, CONF, YPRE, PST);
    fuse2<<<(BATCH * CVCH * NPIX + 255) / 256, 256>>>(YPRE, PST, YPAD);

    gemm_tf32<false><<<dim3(32, 2, 2), 256>>>(WT + WT_R1, 0, 256, 256, YPAD, (long)CVCH * PADN, PADN,
        (const float*)d_in[23], T1PAD, (long)CVCH * PADN, 256, 9, 1, 1, 1.f, 1, nullptr, 0);
    gemm_tf32<false><<<dim3(32, 2, 2), 256>>>(WT + WT_R2, 0, 256, 256, T1PAD, (long)CVCH * PADN, PADN,
        (const float*)d_in[25], res, sCV, 256, 9, 0, 0, 1.f, 0, YPAD, (long)CVCH * PADN);
}